// round 13
// baseline (speedup 1.0000x reference)
#include <cuda_runtime.h>
#include <cuda_fp16.h>
#include <cstdint>

#define NB 64
#define NS 512
#define NTA 8
#define ND 768

// ------------------------------------------------------------------
// scratch (static __device__; no allocations allowed)
// ------------------------------------------------------------------
__device__ float g_mlen[NB], g_alen[NB];
__device__ float g_va[NB * ND], g_vs[NB * ND], g_ctx[NB * ND];
__device__ float g_scores[NB * NS];
__device__ float g_vns[NB * ND], g_vms[NB * ND];

// fp16 operands
__device__ __half g_Ah[(size_t)NB * NS * ND];
__device__ __half g_Bh[(size_t)ND * ND];      // [n][k] = W1_m[k][n]
__device__ __half g_Wch[(size_t)2 * ND * ND]; // W1_a, W1_s in [k][d] (fp16)

// ------------------------------------------------------------------
// PTX helpers (baseline ISA only)
// ------------------------------------------------------------------
__device__ __forceinline__ uint32_t smem_u32(const void* p) {
    uint32_t a;
    asm("{ .reg .u64 t; cvta.to.shared.u64 t, %1; cvt.u32.u64 %0, t; }" : "=r"(a) : "l"(p));
    return a;
}
__device__ __forceinline__ void cp16(uint32_t dst, const void* src) {
    asm volatile("cp.async.cg.shared.global [%0], [%1], 16;" :: "r"(dst), "l"(src));
}
#define CP_COMMIT() asm volatile("cp.async.commit_group;" ::: "memory")
#define CP_WAIT1()  asm volatile("cp.async.wait_group 1;" ::: "memory")

__device__ __forceinline__ void ldsm4(uint32_t& r0, uint32_t& r1, uint32_t& r2, uint32_t& r3,
                                      uint32_t addr) {
    asm volatile("ldmatrix.sync.aligned.m8n8.x4.shared.b16 {%0,%1,%2,%3}, [%4];"
                 : "=r"(r0), "=r"(r1), "=r"(r2), "=r"(r3) : "r"(addr));
}
// fp16-accumulate MMA (2 c-regs, f16x2 each)
__device__ __forceinline__ void mma16816h(uint32_t* c, uint32_t a0, uint32_t a1, uint32_t a2,
                                          uint32_t a3, uint32_t b0, uint32_t b1) {
    asm volatile(
        "mma.sync.aligned.m16n8k16.row.col.f16.f16.f16.f16 "
        "{%0,%1}, {%2,%3,%4,%5}, {%6,%7}, {%0,%1};"
        : "+r"(c[0]), "+r"(c[1])
        : "r"(a0), "r"(a1), "r"(a2), "r"(a3), "r"(b0), "r"(b1));
}
__device__ __forceinline__ uint32_t tanh2_f16(uint32_t x) {
    uint32_t y;
    asm("tanh.approx.f16x2 %0, %1;" : "=r"(y) : "r"(x));
    return y;
}

// ------------------------------------------------------------------
// k_head: means+convert / W1_m transpose / lens / W1_a,W1_s fp16 convert
//   [0,384): means (b, d-block) + fp16 convert of memory
//   [384,960): W1_m transpose+fp16 (24x24 tiles)
//   [960,1024): global lens
//   [1024,1312): fp16 convert of W1_a,W1_s (elementwise)
// ------------------------------------------------------------------
__global__ __launch_bounds__(512) void k_head(const float* __restrict__ mem,
                                              const float* __restrict__ asp,
                                              const int* __restrict__ ids,
                                              const int* __restrict__ tids,
                                              const float* __restrict__ W1) {
    int blk = blockIdx.x;
    int tid = threadIdx.x;
    if (blk < 384) {
        int b = blk / 6;
        int db = blk % 6;
        __shared__ float sp[4][128];
        __shared__ float s_ml, s_al;
        float* red = &sp[0][0];
        red[tid] = (ids[b * NS + tid] != 0) ? 1.0f : 0.0f;
        __syncthreads();
        for (int o = 256; o > 0; o >>= 1) {
            if (tid < o) red[tid] += red[tid + o];
            __syncthreads();
        }
        if (tid == 0) {
            s_ml = fmaxf(red[0], 1.0f);
            int a = 0;
#pragma unroll
            for (int t = 0; t < NTA; t++) a += (tids[b * NTA + t] != 0);
            s_al = fmaxf((float)a, 1.0f);
        }
        __syncthreads();
        float mlen = s_ml, alen = s_al;
        __syncthreads();
        int d = db * 128 + (tid & 127);
        int q = tid >> 7;
        float acc = 0.f;
        const float* p = mem + ((size_t)b * NS + q * 128) * ND + d;
        __half* ah = g_Ah + ((size_t)b * NS + q * 128) * ND + d;
#pragma unroll 8
        for (int s = 0; s < 128; s++) {
            float v = p[(size_t)s * ND];
            acc += v;
            ah[(size_t)s * ND] = __float2half_rn(v);
        }
        sp[q][tid & 127] = acc;
        __syncthreads();
        if (q == 0) {
            float tot = sp[0][tid] + sp[1][tid] + sp[2][tid] + sp[3][tid];
            g_vs[b * ND + d] = tot / mlen;
            float a = 0.f;
            const float* ap = asp + ((size_t)b * NTA) * ND + d;
#pragma unroll
            for (int t = 0; t < NTA; t++) a += ap[(size_t)t * ND];
            g_va[b * ND + d] = a / alen;
        }
    } else if (blk < 960) {
        __shared__ float t[32][33];
        int bb = blk - 384;
        int k0 = (bb % 24) * 32, n0 = (bb / 24) * 32;
        int tx = tid & 31, ty = tid >> 5;
        for (int i = ty; i < 32; i += 16)
            t[i][tx] = W1[(size_t)(k0 + i) * ND + n0 + tx];
        __syncthreads();
        for (int i = ty; i < 32; i += 16)
            g_Bh[(size_t)(n0 + i) * ND + k0 + tx] = __float2half_rn(t[tx][i]);
    } else if (blk < 1024) {
        int b = blk - 960;
        __shared__ float red[512];
        red[tid] = (ids[b * NS + tid] != 0) ? 1.0f : 0.0f;
        __syncthreads();
        for (int o = 256; o > 0; o >>= 1) {
            if (tid < o) red[tid] += red[tid + o];
            __syncthreads();
        }
        if (tid == 0) {
            g_mlen[b] = fmaxf(red[0], 1.0f);
            int a = 0;
#pragma unroll
            for (int t = 0; t < NTA; t++) a += (tids[b * NTA + t] != 0);
            g_alen[b] = fmaxf((float)a, 1.0f);
        }
    } else {
        // fp16 convert of W1_a/W1_s: 288 blocks x 512 thr x 8 elems
        size_t base = (size_t)(blk - 1024) * 4096 + (size_t)tid * 8;
        const float* src = W1 + (size_t)ND * ND + base;
        float4 v0 = *(const float4*)src;
        float4 v1 = *(const float4*)(src + 4);
        __half h[8];
        h[0] = __float2half_rn(v0.x); h[1] = __float2half_rn(v0.y);
        h[2] = __float2half_rn(v0.z); h[3] = __float2half_rn(v0.w);
        h[4] = __float2half_rn(v1.x); h[5] = __float2half_rn(v1.y);
        h[6] = __float2half_rn(v1.z); h[7] = __float2half_rn(v1.w);
        *(uint4*)(g_Wch + base) = *(uint4*)h;
    }
}

// ------------------------------------------------------------------
// ctx = v_a @ W1_a + v_s @ W1_s + b1   (fp16 weights)
// grid (ND/128, NB/2), 512 thr = 128 d x 4 q; 2 b's/thread
// ------------------------------------------------------------------
__global__ __launch_bounds__(512) void k_ctx(const float* __restrict__ b1) {
    __shared__ float sp[4][128][2];
    int tid = threadIdx.x;
    int dt = tid & 127;
    int d = blockIdx.x * 128 + dt;
    int q = tid >> 7;
    int b0 = blockIdx.y * 2;
    const __half* W = g_Wch + (size_t)(q >> 1) * ND * ND + d;
    const float* vb = ((q >> 1) ? g_vs : g_va) + (size_t)b0 * ND;
    int k0 = (q & 1) * 384;
    float a0 = 0.f, a1 = 0.f;
#pragma unroll 4
    for (int k = 0; k < 384; k++) {
        float w = __half2float(W[(size_t)(k0 + k) * ND]);
        a0 = fmaf(vb[k0 + k], w, a0);
        a1 = fmaf(vb[ND + k0 + k], w, a1);
    }
    sp[q][dt][0] = a0;
    sp[q][dt][1] = a1;
    __syncthreads();
    if (q == 0) {
        float bb = b1[d];
#pragma unroll
        for (int i = 0; i < 2; i++) {
            float s = sp[0][dt][i] + sp[1][dt][i] + sp[2][dt][i] + sp[3][dt][i] + bb;
            g_ctx[(b0 + i) * ND + d] = s;
        }
    }
}

// ------------------------------------------------------------------
// fused scores: fp16-acc MMA, 3-buffer cp.async, 1 barrier/stage
// 512 thr = 4x4 warp grid. MT=128, NTILE=128, KC=64, 72 flat stages.
// ------------------------------------------------------------------
#define MT 128
#define NTILE 128
#define KC 64
#define NCHUNKS (ND / NTILE)   // 6
#define KSTEPS (ND / KC)       // 12
#define NSTAGES (NCHUNKS * KSTEPS)  // 72
#define APAD 144

#define OFF_A 0
#define OFF_B 18432
#define BUFSZ 36864
#define OFF_CTX (3 * BUFSZ)          // 110592
#define OFF_W2  (OFF_CTX + 3072)     // 113664
#define OFF_RED (OFF_W2 + 3072)      // 116736
#define SMEMSZ  (OFF_RED + 2048)     // 118784

struct ScoreCtx {
    const __half* gA;
    uint32_t sbase;
};

__device__ __forceinline__ void stage_tiles(const ScoreCtx& sc, int nbase, int k0, int buf) {
    int tid = threadIdx.x;
    uint32_t sb = sc.sbase + buf * BUFSZ;
#pragma unroll
    for (int t = 0; t < 2; t++) {
        int i = tid + t * 512;
        int r = i >> 3, c = i & 7;
        uint32_t d = sb + r * APAD + c * 16;
        cp16(d + OFF_A, sc.gA + (size_t)r * ND + k0 + c * 8);
        cp16(d + OFF_B, g_Bh + (size_t)(nbase + r) * ND + k0 + c * 8);
    }
}

__global__ void __launch_bounds__(512, 1) k_scores(const float* __restrict__ w2) {
    extern __shared__ char smem[];
    const int tid = threadIdx.x;
    const int b = blockIdx.y;
    const int s0 = blockIdx.x * MT;
    const int lane = tid & 31, wid = tid >> 5;
    const int warp_m = wid & 3, warp_n = wid >> 2;   // 4 x 4 warps

    float* sctx = (float*)(smem + OFF_CTX);
    float* sw2p = (float*)(smem + OFF_W2);
    for (int i = tid; i < ND; i += 512) {
        sctx[i] = g_ctx[b * ND + i];
        sw2p[i] = w2[i];
    }

    ScoreCtx sc;
    sc.gA = g_Ah + ((size_t)b * NS + s0) * ND;
    sc.sbase = smem_u32(smem);

    const float mlen = g_mlen[b];
    float loc[2][2], rowsum[2][2];
#pragma unroll
    for (int mt = 0; mt < 2; mt++)
#pragma unroll
        for (int h = 0; h < 2; h++) {
            float srow = (float)(s0 + warp_m * 32 + mt * 16 + h * 8 + (lane >> 2));
            loc[mt][h] = (srow < mlen) ? (1.0f - srow / mlen) : 1.0f;
            rowsum[mt][h] = 0.f;
        }

    const int a_row = warp_m * 32 + (lane & 7) + ((lane >> 3) & 1) * 8;
    const int a_halfoff = (lane >> 4) * 16;
    const int b_row = warp_n * 32 + (lane & 7) + (lane >> 4) * 8;
    const int b_halfoff = ((lane >> 3) & 1) * 16;

    __syncthreads();

    // prologue: stage t=0, t=1
    stage_tiles(sc, 0, 0, 0);
    CP_COMMIT();
    stage_tiles(sc, 0, KC, 1);
    CP_COMMIT();

    float acc[2][4][4];
    uint32_t acch[2][4][2];
    int chunk = 0, ks = 0;

    for (int t = 0; t < NSTAGES; t++) {
        if (ks == 0) {
#pragma unroll
            for (int mt = 0; mt < 2; mt++)
#pragma unroll
                for (int nt = 0; nt < 4; nt++) {
#pragma unroll
                    for (int j = 0; j < 4; j++) acc[mt][nt][j] = 0.f;
                    acch[mt][nt][0] = 0u;
                    acch[mt][nt][1] = 0u;
                }
        }

        CP_WAIT1();          // stage t complete (≤1 pending: t+1)
        __syncthreads();     // all warps see data; all done reading buf (t+2)%3

        if (t + 2 < NSTAGES) {
            int t2 = t + 2;
            int c2 = t2 / KSTEPS, k2 = t2 % KSTEPS;
            stage_tiles(sc, c2 * NTILE, k2 * KC, t2 % 3);
            CP_COMMIT();
        }

        const uint32_t sb = sc.sbase + (t % 3) * BUFSZ;
#pragma unroll
        for (int kk = 0; kk < 4; kk++) {
            const int kb = kk * 32;
            uint32_t ar[2][4], br[2][4];
#pragma unroll
            for (int mt = 0; mt < 2; mt++)
                ldsm4(ar[mt][0], ar[mt][1], ar[mt][2], ar[mt][3],
                      sb + OFF_A + (a_row + mt * 16) * APAD + kb + a_halfoff);
#pragma unroll
            for (int nt2 = 0; nt2 < 2; nt2++)
                ldsm4(br[nt2][0], br[nt2][1], br[nt2][2], br[nt2][3],
                      sb + OFF_B + (b_row + nt2 * 16) * APAD + kb + b_halfoff);
#pragma unroll
            for (int mt = 0; mt < 2; mt++)
#pragma unroll
                for (int nt2 = 0; nt2 < 2; nt2++)
#pragma unroll
                    for (int s = 0; s < 2; s++)
                        mma16816h(acch[mt][nt2 * 2 + s], ar[mt][0], ar[mt][1], ar[mt][2],
                                  ar[mt][3], br[nt2][2 * s], br[nt2][2 * s + 1]);
        }

        // promote f16 partials to f32 every 3 ks (K=192 chain)
        if ((ks % 3) == 2) {
#pragma unroll
            for (int mt = 0; mt < 2; mt++)
#pragma unroll
                for (int nt = 0; nt < 4; nt++) {
                    float2 p0 = __half22float2(*(__half2*)&acch[mt][nt][0]);
                    float2 p1 = __half22float2(*(__half2*)&acch[mt][nt][1]);
                    acc[mt][nt][0] += p0.x;
                    acc[mt][nt][1] += p0.y;
                    acc[mt][nt][2] += p1.x;
                    acc[mt][nt][3] += p1.y;
                    acch[mt][nt][0] = 0u;
                    acch[mt][nt][1] = 0u;
                }
        }

        if (ks == KSTEPS - 1) {
            // chunk epilogue: tanh (f16x2) + dot with w2
            const int nbase = chunk * NTILE;
#pragma unroll
            for (int mt = 0; mt < 2; mt++) {
#pragma unroll
                for (int nt = 0; nt < 4; nt++) {
                    const int c0 = nbase + warp_n * 32 + nt * 8 + (lane & 3) * 2;
                    const float2 cx = *(const float2*)&sctx[c0];
                    const float2 wv = *(const float2*)&sw2p[c0];
                    {
                        float u0 = fmaf(loc[mt][0], acc[mt][nt][0], cx.x);
                        float u1 = fmaf(loc[mt][0], acc[mt][nt][1], cx.y);
                        __half2 hp = __floats2half2_rn(u0, u1);
                        uint32_t th = tanh2_f16(*(uint32_t*)&hp);
                        float2 tf = __half22float2(*(__half2*)&th);
                        rowsum[mt][0] = fmaf(tf.x, wv.x, fmaf(tf.y, wv.y, rowsum[mt][0]));
                    }
                    {
                        float u2 = fmaf(loc[mt][1], acc[mt][nt][2], cx.x);
                        float u3 = fmaf(loc[mt][1], acc[mt][nt][3], cx.y);
                        __half2 hp = __floats2half2_rn(u2, u3);
                        uint32_t th = tanh2_f16(*(uint32_t*)&hp);
                        float2 tf = __half22float2(*(__half2*)&th);
                        rowsum[mt][1] = fmaf(tf.x, wv.x, fmaf(tf.y, wv.y, rowsum[mt][1]));
                    }
                }
            }
            chunk++;
            ks = 0;
        } else {
            ks++;
        }
    }

    // reduce quad lanes, then across 4 warp_n via smem
    float* red = (float*)(smem + OFF_RED);
#pragma unroll
    for (int mt = 0; mt < 2; mt++)
#pragma unroll
        for (int h = 0; h < 2; h++) {
            float v = rowsum[mt][h];
            v += __shfl_xor_sync(0xffffffffu, v, 1);
            v += __shfl_xor_sync(0xffffffffu, v, 2);
            if ((lane & 3) == 0) {
                int lrow = warp_m * 32 + mt * 16 + h * 8 + (lane >> 2);
                red[lrow * 4 + warp_n] = v;
            }
        }
    __syncthreads();
    if (tid < MT)
        g_scores[b * NS + s0 + tid] =
            (red[tid * 4] + red[tid * 4 + 1]) + (red[tid * 4 + 2] + red[tid * 4 + 3]);
}

// ------------------------------------------------------------------
// v_ts + v_ns with inline softmax.  grid (6, 64) = 384 CTAs.
// ------------------------------------------------------------------
__global__ __launch_bounds__(512) void k_vts() {
    int b = blockIdx.y;
    int dc = blockIdx.x;
    int tid = threadIdx.x;
    __shared__ float sw[NS];
    __shared__ float red[512];
    __shared__ float sp[8][64][2];
    float mlen = g_mlen[b];

    float v = g_scores[b * NS + tid];
    red[tid] = v;
    __syncthreads();
    for (int o = 256; o > 0; o >>= 1) {
        if (tid < o) red[tid] = fmaxf(red[tid], red[tid + o]);
        __syncthreads();
    }
    float m = red[0];
    __syncthreads();
    float e = expf(v - m);
    red[tid] = e;
    __syncthreads();
    for (int o = 256; o > 0; o >>= 1) {
        if (tid < o) red[tid] += red[tid + o];
        __syncthreads();
    }
    float inv = 1.0f / red[0];
    float s = (float)tid;
    float l = (s < mlen) ? (1.0f - s / mlen) : 1.0f;
    sw[tid] = e * inv * l;
    __syncthreads();

    int sq = tid >> 6;
    int dd = tid & 63;
    int d = dc * 128 + dd * 2;
    const __half2* p = (const __half2*)(g_Ah + ((size_t)b * NS + sq * 64) * ND + d);
    float a0 = 0.f, a1 = 0.f;
#pragma unroll 8
    for (int s2 = 0; s2 < 64; s2++) {
        float2 h = __half22float2(p[(size_t)s2 * (ND / 2)]);
        float w = sw[sq * 64 + s2];
        a0 = fmaf(w, h.x, a0);
        a1 = fmaf(w, h.y, a1);
    }
    sp[sq][dd][0] = a0;
    sp[sq][dd][1] = a1;
    __syncthreads();
    if (sq == 0) {
        float t0 = 0.f, t1 = 0.f;
#pragma unroll
        for (int i = 0; i < 8; i++) {
            t0 += sp[i][dd][0];
            t1 += sp[i][dd][1];
        }
        g_vns[b * ND + d] = t0 + g_vs[b * ND + d];
        g_vns[b * ND + d + 1] = t1 + g_vs[b * ND + d + 1];
    }
}

// ------------------------------------------------------------------
// v_ms = tanh(v_ns @ Wm + bm)   [unchanged]
// ------------------------------------------------------------------
__global__ __launch_bounds__(512) void k_vms(const float* __restrict__ Wm,
                                             const float* __restrict__ bm) {
    __shared__ float sp[4][128][2];
    int tid = threadIdx.x;
    int dt = tid & 127;
    int d = blockIdx.x * 128 + dt;
    int q = tid >> 7;
    int b0 = blockIdx.y * 2;
    const float* vb = g_vns + (size_t)b0 * ND;
    int k0 = q * 192;
    float a0 = 0.f, a1 = 0.f;
#pragma unroll 4
    for (int k = 0; k < 192; k++) {
        float w = Wm[(size_t)(k0 + k) * ND + d];
        a0 = fmaf(vb[k0 + k], w, a0);
        a1 = fmaf(vb[ND + k0 + k], w, a1);
    }
    sp[q][dt][0] = a0;
    sp[q][dt][1] = a1;
    __syncthreads();
    if (q == 0) {
        float bb = bm[d];
#pragma unroll
        for (int i = 0; i < 2; i++) {
            float s = sp[0][dt][i] + sp[1][dt][i] + sp[2][dt][i] + sp[3][dt][i] + bb;
            g_vms[(b0 + i) * ND + d] = tanhf(s);
        }
    }
}

// ------------------------------------------------------------------
// logits: 64 CTAs (one per b), 256 thr, smem tree reduce
// ------------------------------------------------------------------
__global__ __launch_bounds__(256) void k_logits(const float* __restrict__ Wd,
                                                const float* __restrict__ bd,
                                                float* __restrict__ out) {
    int b = blockIdx.x;
    int tid = threadIdx.x;
    __shared__ float red[256][3];
    float a0 = 0.f, a1 = 0.f, a2 = 0.f;
    const float* v = g_vms + b * ND;
    for (int d = tid; d < ND; d += 256) {
        float vv = v[d];
        a0 = fmaf(vv, Wd[d * 3 + 0], a0);
        a1 = fmaf(vv, Wd[d * 3 + 1], a1);
        a2 = fmaf(vv, Wd[d * 3 + 2], a2);
    }
    red[tid][0] = a0;
    red[tid][1] = a1;
    red[tid][2] = a2;
    __syncthreads();
    for (int o = 128; o > 0; o >>= 1) {
        if (tid < o) {
            red[tid][0] += red[tid + o][0];
            red[tid][1] += red[tid + o][1];
            red[tid][2] += red[tid + o][2];
        }
        __syncthreads();
    }
    if (tid < 3)
        out[b * 3 + tid] = red[0][tid] + bd[tid];
}

// ------------------------------------------------------------------
// launch  (6 kernels; #4 = k_vts -> ncu capture)
// ------------------------------------------------------------------
extern "C" void kernel_launch(void* const* d_in, const int* in_sizes, int n_in,
                              void* d_out, int out_size) {
    (void)in_sizes; (void)n_in; (void)out_size;
    const float* mem  = (const float*)d_in[0];
    const float* asp  = (const float*)d_in[1];
    const int* ids    = (const int*)d_in[2];
    const int* tids   = (const int*)d_in[3];
    const float* W1 = (const float*)d_in[4];
    const float* b1 = (const float*)d_in[5];
    const float* w2 = (const float*)d_in[6];
    const float* Wm = (const float*)d_in[7];
    const float* bm = (const float*)d_in[8];
    const float* Wd = (const float*)d_in[9];
    const float* bd = (const float*)d_in[10];
    float* out = (float*)d_out;

    cudaFuncSetAttribute(k_scores, cudaFuncAttributeMaxDynamicSharedMemorySize, SMEMSZ);

    k_head<<<1312, 512>>>(mem, asp, ids, tids, W1);
    k_ctx<<<dim3(ND / 128, NB / 2), 512>>>(b1);
    k_scores<<<dim3(NS / MT, NB), 512, SMEMSZ>>>(w2);
    k_vts<<<dim3(6, NB), 512>>>();
    k_vms<<<dim3(ND / 128, NB / 2), 512>>>(Wm, bm);
    k_logits<<<NB, 256>>>(Wd, bd, out);
}

// round 14
// speedup vs baseline: 1.0284x; 1.0284x over previous
#include <cuda_runtime.h>
#include <cuda_fp16.h>
#include <cstdint>

#define NB 64
#define NS 512
#define NTA 8
#define ND 768

// ------------------------------------------------------------------
// scratch (static __device__; no allocations allowed)
// ------------------------------------------------------------------
__device__ float g_mlen[NB], g_alen[NB];
__device__ float g_va[NB * ND], g_vs[NB * ND], g_ctx[NB * ND];
__device__ float g_scores[NB * NS];
__device__ float g_vns[NB * ND], g_vms[NB * ND];

// fp16 operands
__device__ __half g_Ah[(size_t)NB * NS * ND];
__device__ __half g_Bh[(size_t)ND * ND];      // [n][k] = W1_m[k][n]
__device__ __half g_Wch[(size_t)2 * ND * ND]; // W1_a, W1_s in [k][d] (fp16)

// ------------------------------------------------------------------
// PTX helpers (baseline ISA only)
// ------------------------------------------------------------------
__device__ __forceinline__ uint32_t smem_u32(const void* p) {
    uint32_t a;
    asm("{ .reg .u64 t; cvta.to.shared.u64 t, %1; cvt.u32.u64 %0, t; }" : "=r"(a) : "l"(p));
    return a;
}
__device__ __forceinline__ void cp16(uint32_t dst, const void* src) {
    asm volatile("cp.async.cg.shared.global [%0], [%1], 16;" :: "r"(dst), "l"(src));
}
#define CP_COMMIT() asm volatile("cp.async.commit_group;" ::: "memory")
#define CP_WAIT1()  asm volatile("cp.async.wait_group 1;" ::: "memory")
#define CP_WAIT0()  asm volatile("cp.async.wait_group 0;" ::: "memory")

__device__ __forceinline__ void ldsm4(uint32_t& r0, uint32_t& r1, uint32_t& r2, uint32_t& r3,
                                      uint32_t addr) {
    asm volatile("ldmatrix.sync.aligned.m8n8.x4.shared.b16 {%0,%1,%2,%3}, [%4];"
                 : "=r"(r0), "=r"(r1), "=r"(r2), "=r"(r3) : "r"(addr));
}
// fp16-accumulate MMA (2 c-regs, f16x2 each)
__device__ __forceinline__ void mma16816h(uint32_t* c, uint32_t a0, uint32_t a1, uint32_t a2,
                                          uint32_t a3, uint32_t b0, uint32_t b1) {
    asm volatile(
        "mma.sync.aligned.m16n8k16.row.col.f16.f16.f16.f16 "
        "{%0,%1}, {%2,%3,%4,%5}, {%6,%7}, {%0,%1};"
        : "+r"(c[0]), "+r"(c[1])
        : "r"(a0), "r"(a1), "r"(a2), "r"(a3), "r"(b0), "r"(b1));
}
__device__ __forceinline__ uint32_t tanh2_f16(uint32_t x) {
    uint32_t y;
    asm("tanh.approx.f16x2 %0, %1;" : "=r"(y) : "r"(x));
    return y;
}

// ------------------------------------------------------------------
// k_head: means+convert / W1_m transpose / lens / W1_a,W1_s fp16 convert
// ------------------------------------------------------------------
__global__ __launch_bounds__(512) void k_head(const float* __restrict__ mem,
                                              const float* __restrict__ asp,
                                              const int* __restrict__ ids,
                                              const int* __restrict__ tids,
                                              const float* __restrict__ W1) {
    int blk = blockIdx.x;
    int tid = threadIdx.x;
    if (blk < 384) {
        int b = blk / 6;
        int db = blk % 6;
        __shared__ float sp[4][128];
        __shared__ float s_ml, s_al;
        float* red = &sp[0][0];
        red[tid] = (ids[b * NS + tid] != 0) ? 1.0f : 0.0f;
        __syncthreads();
        for (int o = 256; o > 0; o >>= 1) {
            if (tid < o) red[tid] += red[tid + o];
            __syncthreads();
        }
        if (tid == 0) {
            s_ml = fmaxf(red[0], 1.0f);
            int a = 0;
#pragma unroll
            for (int t = 0; t < NTA; t++) a += (tids[b * NTA + t] != 0);
            s_al = fmaxf((float)a, 1.0f);
        }
        __syncthreads();
        float mlen = s_ml, alen = s_al;
        __syncthreads();
        int d = db * 128 + (tid & 127);
        int q = tid >> 7;
        float acc = 0.f;
        const float* p = mem + ((size_t)b * NS + q * 128) * ND + d;
        __half* ah = g_Ah + ((size_t)b * NS + q * 128) * ND + d;
#pragma unroll 8
        for (int s = 0; s < 128; s++) {
            float v = p[(size_t)s * ND];
            acc += v;
            ah[(size_t)s * ND] = __float2half_rn(v);
        }
        sp[q][tid & 127] = acc;
        __syncthreads();
        if (q == 0) {
            float tot = sp[0][tid] + sp[1][tid] + sp[2][tid] + sp[3][tid];
            g_vs[b * ND + d] = tot / mlen;
            float a = 0.f;
            const float* ap = asp + ((size_t)b * NTA) * ND + d;
#pragma unroll
            for (int t = 0; t < NTA; t++) a += ap[(size_t)t * ND];
            g_va[b * ND + d] = a / alen;
        }
    } else if (blk < 960) {
        __shared__ float t[32][33];
        int bb = blk - 384;
        int k0 = (bb % 24) * 32, n0 = (bb / 24) * 32;
        int tx = tid & 31, ty = tid >> 5;
        for (int i = ty; i < 32; i += 16)
            t[i][tx] = W1[(size_t)(k0 + i) * ND + n0 + tx];
        __syncthreads();
        for (int i = ty; i < 32; i += 16)
            g_Bh[(size_t)(n0 + i) * ND + k0 + tx] = __float2half_rn(t[tx][i]);
    } else if (blk < 1024) {
        int b = blk - 960;
        __shared__ float red[512];
        red[tid] = (ids[b * NS + tid] != 0) ? 1.0f : 0.0f;
        __syncthreads();
        for (int o = 256; o > 0; o >>= 1) {
            if (tid < o) red[tid] += red[tid + o];
            __syncthreads();
        }
        if (tid == 0) {
            g_mlen[b] = fmaxf(red[0], 1.0f);
            int a = 0;
#pragma unroll
            for (int t = 0; t < NTA; t++) a += (tids[b * NTA + t] != 0);
            g_alen[b] = fmaxf((float)a, 1.0f);
        }
    } else {
        // fp16 convert of W1_a/W1_s: 288 blocks x 512 thr x 8 elems
        size_t base = (size_t)(blk - 1024) * 4096 + (size_t)tid * 8;
        const float* src = W1 + (size_t)ND * ND + base;
        float4 v0 = *(const float4*)src;
        float4 v1 = *(const float4*)(src + 4);
        __half h[8];
        h[0] = __float2half_rn(v0.x); h[1] = __float2half_rn(v0.y);
        h[2] = __float2half_rn(v0.z); h[3] = __float2half_rn(v0.w);
        h[4] = __float2half_rn(v1.x); h[5] = __float2half_rn(v1.y);
        h[6] = __float2half_rn(v1.z); h[7] = __float2half_rn(v1.w);
        *(uint4*)(g_Wch + base) = *(uint4*)h;
    }
}

// ------------------------------------------------------------------
// ctx = v_a @ W1_a + v_s @ W1_s + b1   (fp16 weights)
// ------------------------------------------------------------------
__global__ __launch_bounds__(512) void k_ctx(const float* __restrict__ b1) {
    __shared__ float sp[4][128][2];
    int tid = threadIdx.x;
    int dt = tid & 127;
    int d = blockIdx.x * 128 + dt;
    int q = tid >> 7;
    int b0 = blockIdx.y * 2;
    const __half* W = g_Wch + (size_t)(q >> 1) * ND * ND + d;
    const float* vb = ((q >> 1) ? g_vs : g_va) + (size_t)b0 * ND;
    int k0 = (q & 1) * 384;
    float a0 = 0.f, a1 = 0.f;
#pragma unroll 4
    for (int k = 0; k < 384; k++) {
        float w = __half2float(W[(size_t)(k0 + k) * ND]);
        a0 = fmaf(vb[k0 + k], w, a0);
        a1 = fmaf(vb[ND + k0 + k], w, a1);
    }
    sp[q][dt][0] = a0;
    sp[q][dt][1] = a1;
    __syncthreads();
    if (q == 0) {
        float bb = b1[d];
#pragma unroll
        for (int i = 0; i < 2; i++) {
            float s = sp[0][dt][i] + sp[1][dt][i] + sp[2][dt][i] + sp[3][dt][i] + bb;
            g_ctx[(b0 + i) * ND + d] = s;
        }
    }
}

// ------------------------------------------------------------------
// fused scores: fp16-accumulate MMA (promote to f32 every 3 ks)
// 512 thr = 4x4 warp grid. MT=128, NTILE=128, KC=64.   [R12 form]
// ------------------------------------------------------------------
#define MT 128
#define NTILE 128
#define KC 64
#define NCHUNKS (ND / NTILE)   // 6
#define KSTEPS (ND / KC)       // 12
#define APAD 144

#define OFF_A 0
#define OFF_B 18432
#define BUFSZ 36864
#define OFF_CTX (2 * BUFSZ)
#define OFF_W2  (OFF_CTX + 3072)
#define OFF_RED (OFF_W2 + 3072)
#define SMEMSZ  (OFF_RED + 2048)

struct ScoreCtx {
    const __half* gA;
    uint32_t sbase;
};

__device__ __forceinline__ void stage_tiles(const ScoreCtx& sc, int nbase, int k0, int buf) {
    int tid = threadIdx.x;
    uint32_t sb = sc.sbase + buf * BUFSZ;
#pragma unroll
    for (int t = 0; t < 2; t++) {
        int i = tid + t * 512;
        int r = i >> 3, c = i & 7;
        uint32_t d = sb + r * APAD + c * 16;
        cp16(d + OFF_A, sc.gA + (size_t)r * ND + k0 + c * 8);
        cp16(d + OFF_B, g_Bh + (size_t)(nbase + r) * ND + k0 + c * 8);
    }
}

__global__ void __launch_bounds__(512, 1) k_scores(const float* __restrict__ w2) {
    extern __shared__ char smem[];
    const int tid = threadIdx.x;
    const int b = blockIdx.y;
    const int s0 = blockIdx.x * MT;
    const int lane = tid & 31, wid = tid >> 5;
    const int warp_m = wid & 3, warp_n = wid >> 2;   // 4 x 4 warps

    float* sctx = (float*)(smem + OFF_CTX);
    float* sw2p = (float*)(smem + OFF_W2);
    for (int i = tid; i < ND; i += 512) {
        sctx[i] = g_ctx[b * ND + i];
        sw2p[i] = w2[i];
    }

    ScoreCtx sc;
    sc.gA = g_Ah + ((size_t)b * NS + s0) * ND;
    sc.sbase = smem_u32(smem);

    const float mlen = g_mlen[b];
    float loc[2][2], rowsum[2][2];
#pragma unroll
    for (int mt = 0; mt < 2; mt++)
#pragma unroll
        for (int h = 0; h < 2; h++) {
            float srow = (float)(s0 + warp_m * 32 + mt * 16 + h * 8 + (lane >> 2));
            loc[mt][h] = (srow < mlen) ? (1.0f - srow / mlen) : 1.0f;
            rowsum[mt][h] = 0.f;
        }

    const int a_row = warp_m * 32 + (lane & 7) + ((lane >> 3) & 1) * 8;
    const int a_halfoff = (lane >> 4) * 16;
    const int b_row = warp_n * 32 + (lane & 7) + (lane >> 4) * 8;
    const int b_halfoff = ((lane >> 3) & 1) * 16;

    __syncthreads();

    stage_tiles(sc, 0, 0, 0);
    CP_COMMIT();

    for (int chunk = 0; chunk < NCHUNKS; chunk++) {
        const int nbase = chunk * NTILE;
        float acc[2][4][4];
        uint32_t acch[2][4][2];
#pragma unroll
        for (int mt = 0; mt < 2; mt++)
#pragma unroll
            for (int nt = 0; nt < 4; nt++) {
#pragma unroll
                for (int j = 0; j < 4; j++) acc[mt][nt][j] = 0.f;
                acch[mt][nt][0] = 0u;
                acch[mt][nt][1] = 0u;
            }

        for (int ks = 0; ks < KSTEPS; ks++) {
            const int buf = ks & 1;
            if (ks + 1 < KSTEPS) {
                stage_tiles(sc, nbase, (ks + 1) * KC, buf ^ 1);
                CP_COMMIT();
                CP_WAIT1();
            } else {
                CP_WAIT0();
            }
            __syncthreads();

            const uint32_t sb = sc.sbase + buf * BUFSZ;
#pragma unroll
            for (int kk = 0; kk < 4; kk++) {
                const int kb = kk * 32;
                uint32_t ar[2][4], br[2][4];
#pragma unroll
                for (int mt = 0; mt < 2; mt++)
                    ldsm4(ar[mt][0], ar[mt][1], ar[mt][2], ar[mt][3],
                          sb + OFF_A + (a_row + mt * 16) * APAD + kb + a_halfoff);
#pragma unroll
                for (int nt2 = 0; nt2 < 2; nt2++)
                    ldsm4(br[nt2][0], br[nt2][1], br[nt2][2], br[nt2][3],
                          sb + OFF_B + (b_row + nt2 * 16) * APAD + kb + b_halfoff);
#pragma unroll
                for (int mt = 0; mt < 2; mt++)
#pragma unroll
                    for (int nt2 = 0; nt2 < 2; nt2++)
#pragma unroll
                        for (int s = 0; s < 2; s++)
                            mma16816h(acch[mt][nt2 * 2 + s], ar[mt][0], ar[mt][1], ar[mt][2],
                                      ar[mt][3], br[nt2][2 * s], br[nt2][2 * s + 1]);
            }
            __syncthreads();

            // promote f16 partials to f32 every 3 ks (K=192 chain)
            if ((ks % 3) == 2) {
#pragma unroll
                for (int mt = 0; mt < 2; mt++)
#pragma unroll
                    for (int nt = 0; nt < 4; nt++) {
                        float2 p0 = __half22float2(*(__half2*)&acch[mt][nt][0]);
                        float2 p1 = __half22float2(*(__half2*)&acch[mt][nt][1]);
                        acc[mt][nt][0] += p0.x;
                        acc[mt][nt][1] += p0.y;
                        acc[mt][nt][2] += p1.x;
                        acc[mt][nt][3] += p1.y;
                        acch[mt][nt][0] = 0u;
                        acch[mt][nt][1] = 0u;
                    }
            }
        }

        if (chunk + 1 < NCHUNKS) {
            stage_tiles(sc, nbase + NTILE, 0, 0);
            CP_COMMIT();
        }

        // epilogue: tanh (f16x2) + dot with w2
#pragma unroll
        for (int mt = 0; mt < 2; mt++) {
#pragma unroll
            for (int nt = 0; nt < 4; nt++) {
                const int c0 = nbase + warp_n * 32 + nt * 8 + (lane & 3) * 2;
                const float2 cx = *(const float2*)&sctx[c0];
                const float2 wv = *(const float2*)&sw2p[c0];
                {
                    float u0 = fmaf(loc[mt][0], acc[mt][nt][0], cx.x);
                    float u1 = fmaf(loc[mt][0], acc[mt][nt][1], cx.y);
                    __half2 hp = __floats2half2_rn(u0, u1);
                    uint32_t th = tanh2_f16(*(uint32_t*)&hp);
                    float2 tf = __half22float2(*(__half2*)&th);
                    rowsum[mt][0] = fmaf(tf.x, wv.x, fmaf(tf.y, wv.y, rowsum[mt][0]));
                }
                {
                    float u2 = fmaf(loc[mt][1], acc[mt][nt][2], cx.x);
                    float u3 = fmaf(loc[mt][1], acc[mt][nt][3], cx.y);
                    __half2 hp = __floats2half2_rn(u2, u3);
                    uint32_t th = tanh2_f16(*(uint32_t*)&hp);
                    float2 tf = __half22float2(*(__half2*)&th);
                    rowsum[mt][1] = fmaf(tf.x, wv.x, fmaf(tf.y, wv.y, rowsum[mt][1]));
                }
            }
        }
    }

    // reduce quad lanes, then across 4 warp_n via smem
    float* red = (float*)(smem + OFF_RED);
#pragma unroll
    for (int mt = 0; mt < 2; mt++)
#pragma unroll
        for (int h = 0; h < 2; h++) {
            float v = rowsum[mt][h];
            v += __shfl_xor_sync(0xffffffffu, v, 1);
            v += __shfl_xor_sync(0xffffffffu, v, 2);
            if ((lane & 3) == 0) {
                int lrow = warp_m * 32 + mt * 16 + h * 8 + (lane >> 2);
                red[lrow * 4 + warp_n] = v;
            }
        }
    __syncthreads();
    if (tid < MT)
        g_scores[b * NS + s0 + tid] =
            (red[tid * 4] + red[tid * 4 + 1]) + (red[tid * 4 + 2] + red[tid * 4 + 3]);
}

// ------------------------------------------------------------------
// v_ts + v_ns with inline softmax.  grid (6, 64) = 384 CTAs.
// ------------------------------------------------------------------
__global__ __launch_bounds__(512) void k_vts() {
    int b = blockIdx.y;
    int dc = blockIdx.x;
    int tid = threadIdx.x;
    __shared__ float sw[NS];
    __shared__ float red[512];
    __shared__ float sp[8][64][2];
    float mlen = g_mlen[b];

    float v = g_scores[b * NS + tid];
    red[tid] = v;
    __syncthreads();
    for (int o = 256; o > 0; o >>= 1) {
        if (tid < o) red[tid] = fmaxf(red[tid], red[tid + o]);
        __syncthreads();
    }
    float m = red[0];
    __syncthreads();
    float e = expf(v - m);
    red[tid] = e;
    __syncthreads();
    for (int o = 256; o > 0; o >>= 1) {
        if (tid < o) red[tid] += red[tid + o];
        __syncthreads();
    }
    float inv = 1.0f / red[0];
    float s = (float)tid;
    float l = (s < mlen) ? (1.0f - s / mlen) : 1.0f;
    sw[tid] = e * inv * l;
    __syncthreads();

    int sq = tid >> 6;
    int dd = tid & 63;
    int d = dc * 128 + dd * 2;
    const __half2* p = (const __half2*)(g_Ah + ((size_t)b * NS + sq * 64) * ND + d);
    float a0 = 0.f, a1 = 0.f;
#pragma unroll 8
    for (int s2 = 0; s2 < 64; s2++) {
        float2 h = __half22float2(p[(size_t)s2 * (ND / 2)]);
        float w = sw[sq * 64 + s2];
        a0 = fmaf(w, h.x, a0);
        a1 = fmaf(w, h.y, a1);
    }
    sp[sq][dd][0] = a0;
    sp[sq][dd][1] = a1;
    __syncthreads();
    if (sq == 0) {
        float t0 = 0.f, t1 = 0.f;
#pragma unroll
        for (int i = 0; i < 8; i++) {
            t0 += sp[i][dd][0];
            t1 += sp[i][dd][1];
        }
        g_vns[b * ND + d] = t0 + g_vs[b * ND + d];
        g_vns[b * ND + d + 1] = t1 + g_vs[b * ND + d + 1];
    }
}

// ------------------------------------------------------------------
// v_ms = tanh(v_ns @ Wm + bm)   [unchanged]
// ------------------------------------------------------------------
__global__ __launch_bounds__(512) void k_vms(const float* __restrict__ Wm,
                                             const float* __restrict__ bm) {
    __shared__ float sp[4][128][2];
    int tid = threadIdx.x;
    int dt = tid & 127;
    int d = blockIdx.x * 128 + dt;
    int q = tid >> 7;
    int b0 = blockIdx.y * 2;
    const float* vb = g_vns + (size_t)b0 * ND;
    int k0 = q * 192;
    float a0 = 0.f, a1 = 0.f;
#pragma unroll 4
    for (int k = 0; k < 192; k++) {
        float w = Wm[(size_t)(k0 + k) * ND + d];
        a0 = fmaf(vb[k0 + k], w, a0);
        a1 = fmaf(vb[ND + k0 + k], w, a1);
    }
    sp[q][dt][0] = a0;
    sp[q][dt][1] = a1;
    __syncthreads();
    if (q == 0) {
        float bb = bm[d];
#pragma unroll
        for (int i = 0; i < 2; i++) {
            float s = sp[0][dt][i] + sp[1][dt][i] + sp[2][dt][i] + sp[3][dt][i] + bb;
            g_vms[(b0 + i) * ND + d] = tanhf(s);
        }
    }
}

// ------------------------------------------------------------------
// logits: 64 CTAs (one per b), 256 thr, smem tree reduce
// ------------------------------------------------------------------
__global__ __launch_bounds__(256) void k_logits(const float* __restrict__ Wd,
                                                const float* __restrict__ bd,
                                                float* __restrict__ out) {
    int b = blockIdx.x;
    int tid = threadIdx.x;
    __shared__ float red[256][3];
    float a0 = 0.f, a1 = 0.f, a2 = 0.f;
    const float* v = g_vms + b * ND;
    for (int d = tid; d < ND; d += 256) {
        float vv = v[d];
        a0 = fmaf(vv, Wd[d * 3 + 0], a0);
        a1 = fmaf(vv, Wd[d * 3 + 1], a1);
        a2 = fmaf(vv, Wd[d * 3 + 2], a2);
    }
    red[tid][0] = a0;
    red[tid][1] = a1;
    red[tid][2] = a2;
    __syncthreads();
    for (int o = 128; o > 0; o >>= 1) {
        if (tid < o) {
            red[tid][0] += red[tid + o][0];
            red[tid][1] += red[tid + o][1];
            red[tid][2] += red[tid + o][2];
        }
        __syncthreads();
    }
    if (tid < 3)
        out[b * 3 + tid] = red[0][tid] + bd[tid];
}

// ------------------------------------------------------------------
// launch  (6 kernels)
// ------------------------------------------------------------------
extern "C" void kernel_launch(void* const* d_in, const int* in_sizes, int n_in,
                              void* d_out, int out_size) {
    (void)in_sizes; (void)n_in; (void)out_size;
    const float* mem  = (const float*)d_in[0];
    const float* asp  = (const float*)d_in[1];
    const int* ids    = (const int*)d_in[2];
    const int* tids   = (const int*)d_in[3];
    const float* W1 = (const float*)d_in[4];
    const float* b1 = (const float*)d_in[5];
    const float* w2 = (const float*)d_in[6];
    const float* Wm = (const float*)d_in[7];
    const float* bm = (const float*)d_in[8];
    const float* Wd = (const float*)d_in[9];
    const float* bd = (const float*)d_in[10];
    float* out = (float*)d_out;

    cudaFuncSetAttribute(k_scores, cudaFuncAttributeMaxDynamicSharedMemorySize, SMEMSZ);

    k_head<<<1312, 512>>>(mem, asp, ids, tids, W1);
    k_ctx<<<dim3(ND / 128, NB / 2), 512>>>(b1);
    k_scores<<<dim3(NS / MT, NB), 512, SMEMSZ>>>(w2);
    k_vts<<<dim3(6, NB), 512>>>();
    k_vms<<<dim3(ND / 128, NB / 2), 512>>>(Wm, bm);
    k_logits<<<NB, 256>>>(Wd, bd, out);
}

// round 15
// speedup vs baseline: 1.0557x; 1.0266x over previous
#include <cuda_runtime.h>
#include <cuda_fp16.h>
#include <cstdint>

#define NB 64
#define NS 512
#define NTA 8
#define ND 768

// ------------------------------------------------------------------
// scratch (static __device__; no allocations allowed)
// ------------------------------------------------------------------
__device__ float g_mlen[NB], g_alen[NB];
__device__ float g_va[NB * ND], g_vs[NB * ND], g_ctx[NB * ND];
__device__ float g_scores[NB * NS];
__device__ float g_vns[NB * ND], g_vms[NB * ND];

// fp16 operands
__device__ __half g_Ah[(size_t)NB * NS * ND];
__device__ __half g_Bh[(size_t)ND * ND];      // [n][k] = W1_m[k][n]
__device__ __half g_Wch[(size_t)2 * ND * ND]; // W1_a, W1_s in [k][d] (fp16)

// ------------------------------------------------------------------
// PTX helpers (baseline ISA only)
// ------------------------------------------------------------------
__device__ __forceinline__ uint32_t smem_u32(const void* p) {
    uint32_t a;
    asm("{ .reg .u64 t; cvta.to.shared.u64 t, %1; cvt.u32.u64 %0, t; }" : "=r"(a) : "l"(p));
    return a;
}
__device__ __forceinline__ void cp16(uint32_t dst, const void* src) {
    asm volatile("cp.async.cg.shared.global [%0], [%1], 16;" :: "r"(dst), "l"(src));
}
#define CP_COMMIT() asm volatile("cp.async.commit_group;" ::: "memory")
#define CP_WAIT1()  asm volatile("cp.async.wait_group 1;" ::: "memory")

__device__ __forceinline__ void ldsm4(uint32_t& r0, uint32_t& r1, uint32_t& r2, uint32_t& r3,
                                      uint32_t addr) {
    asm volatile("ldmatrix.sync.aligned.m8n8.x4.shared.b16 {%0,%1,%2,%3}, [%4];"
                 : "=r"(r0), "=r"(r1), "=r"(r2), "=r"(r3) : "r"(addr));
}
// fp16-accumulate MMA (2 c-regs, f16x2 each)
__device__ __forceinline__ void mma16816h(uint32_t* c, uint32_t a0, uint32_t a1, uint32_t a2,
                                          uint32_t a3, uint32_t b0, uint32_t b1) {
    asm volatile(
        "mma.sync.aligned.m16n8k16.row.col.f16.f16.f16.f16 "
        "{%0,%1}, {%2,%3,%4,%5}, {%6,%7}, {%0,%1};"
        : "+r"(c[0]), "+r"(c[1])
        : "r"(a0), "r"(a1), "r"(a2), "r"(a3), "r"(b0), "r"(b1));
}
__device__ __forceinline__ uint32_t tanh2_f16(uint32_t x) {
    uint32_t y;
    asm("tanh.approx.f16x2 %0, %1;" : "=r"(y) : "r"(x));
    return y;
}

// ------------------------------------------------------------------
// k_head: means+convert / W1_m transpose / lens / W1_a,W1_s fp16 convert
// ------------------------------------------------------------------
__global__ __launch_bounds__(512) void k_head(const float* __restrict__ mem,
                                              const float* __restrict__ asp,
                                              const int* __restrict__ ids,
                                              const int* __restrict__ tids,
                                              const float* __restrict__ W1) {
    int blk = blockIdx.x;
    int tid = threadIdx.x;
    if (blk < 384) {
        int b = blk / 6;
        int db = blk % 6;
        __shared__ float sp[4][128];
        __shared__ float s_ml, s_al;
        float* red = &sp[0][0];
        red[tid] = (ids[b * NS + tid] != 0) ? 1.0f : 0.0f;
        __syncthreads();
        for (int o = 256; o > 0; o >>= 1) {
            if (tid < o) red[tid] += red[tid + o];
            __syncthreads();
        }
        if (tid == 0) {
            s_ml = fmaxf(red[0], 1.0f);
            int a = 0;
#pragma unroll
            for (int t = 0; t < NTA; t++) a += (tids[b * NTA + t] != 0);
            s_al = fmaxf((float)a, 1.0f);
        }
        __syncthreads();
        float mlen = s_ml, alen = s_al;
        __syncthreads();
        int d = db * 128 + (tid & 127);
        int q = tid >> 7;
        float acc = 0.f;
        const float* p = mem + ((size_t)b * NS + q * 128) * ND + d;
        __half* ah = g_Ah + ((size_t)b * NS + q * 128) * ND + d;
#pragma unroll 8
        for (int s = 0; s < 128; s++) {
            float v = p[(size_t)s * ND];
            acc += v;
            ah[(size_t)s * ND] = __float2half_rn(v);
        }
        sp[q][tid & 127] = acc;
        __syncthreads();
        if (q == 0) {
            float tot = sp[0][tid] + sp[1][tid] + sp[2][tid] + sp[3][tid];
            g_vs[b * ND + d] = tot / mlen;
            float a = 0.f;
            const float* ap = asp + ((size_t)b * NTA) * ND + d;
#pragma unroll
            for (int t = 0; t < NTA; t++) a += ap[(size_t)t * ND];
            g_va[b * ND + d] = a / alen;
        }
    } else if (blk < 960) {
        __shared__ float t[32][33];
        int bb = blk - 384;
        int k0 = (bb % 24) * 32, n0 = (bb / 24) * 32;
        int tx = tid & 31, ty = tid >> 5;
        for (int i = ty; i < 32; i += 16)
            t[i][tx] = W1[(size_t)(k0 + i) * ND + n0 + tx];
        __syncthreads();
        for (int i = ty; i < 32; i += 16)
            g_Bh[(size_t)(n0 + i) * ND + k0 + tx] = __float2half_rn(t[tx][i]);
    } else if (blk < 1024) {
        int b = blk - 960;
        __shared__ float red[512];
        red[tid] = (ids[b * NS + tid] != 0) ? 1.0f : 0.0f;
        __syncthreads();
        for (int o = 256; o > 0; o >>= 1) {
            if (tid < o) red[tid] += red[tid + o];
            __syncthreads();
        }
        if (tid == 0) {
            g_mlen[b] = fmaxf(red[0], 1.0f);
            int a = 0;
#pragma unroll
            for (int t = 0; t < NTA; t++) a += (tids[b * NTA + t] != 0);
            g_alen[b] = fmaxf((float)a, 1.0f);
        }
    } else {
        size_t base = (size_t)(blk - 1024) * 4096 + (size_t)tid * 8;
        const float* src = W1 + (size_t)ND * ND + base;
        float4 v0 = *(const float4*)src;
        float4 v1 = *(const float4*)(src + 4);
        __half h[8];
        h[0] = __float2half_rn(v0.x); h[1] = __float2half_rn(v0.y);
        h[2] = __float2half_rn(v0.z); h[3] = __float2half_rn(v0.w);
        h[4] = __float2half_rn(v1.x); h[5] = __float2half_rn(v1.y);
        h[6] = __float2half_rn(v1.z); h[7] = __float2half_rn(v1.w);
        *(uint4*)(g_Wch + base) = *(uint4*)h;
    }
}

// ------------------------------------------------------------------
// ctx = v_a @ W1_a + v_s @ W1_s + b1   (fp16 weights)
// ------------------------------------------------------------------
__global__ __launch_bounds__(512) void k_ctx(const float* __restrict__ b1) {
    __shared__ float sp[4][128][2];
    int tid = threadIdx.x;
    int dt = tid & 127;
    int d = blockIdx.x * 128 + dt;
    int q = tid >> 7;
    int b0 = blockIdx.y * 2;
    const __half* W = g_Wch + (size_t)(q >> 1) * ND * ND + d;
    const float* vb = ((q >> 1) ? g_vs : g_va) + (size_t)b0 * ND;
    int k0 = (q & 1) * 384;
    float a0 = 0.f, a1 = 0.f;
#pragma unroll 4
    for (int k = 0; k < 384; k++) {
        float w = __half2float(W[(size_t)(k0 + k) * ND]);
        a0 = fmaf(vb[k0 + k], w, a0);
        a1 = fmaf(vb[ND + k0 + k], w, a1);
    }
    sp[q][dt][0] = a0;
    sp[q][dt][1] = a1;
    __syncthreads();
    if (q == 0) {
        float bb = b1[d];
#pragma unroll
        for (int i = 0; i < 2; i++) {
            float s = sp[0][dt][i] + sp[1][dt][i] + sp[2][dt][i] + sp[3][dt][i] + bb;
            g_ctx[(b0 + i) * ND + d] = s;
        }
    }
}

// ------------------------------------------------------------------
// null kernel: makes k_scores the 4th launch (ncu capture target)
// ------------------------------------------------------------------
__global__ void k_null() {}

// ------------------------------------------------------------------
// fused scores: fp16-acc MMA, 3-buffer ring, ONE sync per ks
// 512 thr = 4x4 warp grid. MT=128, NTILE=128, KC=64. Two-level loops kept.
// ------------------------------------------------------------------
#define MT 128
#define NTILE 128
#define KC 64
#define NCHUNKS (ND / NTILE)   // 6
#define KSTEPS (ND / KC)       // 12
#define NSTAGES (NCHUNKS * KSTEPS)  // 72
#define APAD 144

#define OFF_A 0
#define OFF_B 18432
#define BUFSZ 36864
#define OFF_CTX (3 * BUFSZ)          // 110592
#define OFF_W2  (OFF_CTX + 3072)
#define OFF_RED (OFF_W2 + 3072)
#define SMEMSZ  (OFF_RED + 2048)     // 120832

struct ScoreCtx {
    const __half* gA;
    uint32_t sbase;
};

__device__ __forceinline__ void stage_tiles(const ScoreCtx& sc, int nbase, int k0, int buf) {
    int tid = threadIdx.x;
    uint32_t sb = sc.sbase + buf * BUFSZ;
#pragma unroll
    for (int t = 0; t < 2; t++) {
        int i = tid + t * 512;
        int r = i >> 3, c = i & 7;
        uint32_t d = sb + r * APAD + c * 16;
        cp16(d + OFF_A, sc.gA + (size_t)r * ND + k0 + c * 8);
        cp16(d + OFF_B, g_Bh + (size_t)(nbase + r) * ND + k0 + c * 8);
    }
}

__global__ void __launch_bounds__(512, 1) k_scores(const float* __restrict__ w2) {
    extern __shared__ char smem[];
    const int tid = threadIdx.x;
    const int b = blockIdx.y;
    const int s0 = blockIdx.x * MT;
    const int lane = tid & 31, wid = tid >> 5;
    const int warp_m = wid & 3, warp_n = wid >> 2;   // 4 x 4 warps

    float* sctx = (float*)(smem + OFF_CTX);
    float* sw2p = (float*)(smem + OFF_W2);
    for (int i = tid; i < ND; i += 512) {
        sctx[i] = g_ctx[b * ND + i];
        sw2p[i] = w2[i];
    }

    ScoreCtx sc;
    sc.gA = g_Ah + ((size_t)b * NS + s0) * ND;
    sc.sbase = smem_u32(smem);

    const float mlen = g_mlen[b];
    float loc[2][2], rowsum[2][2];
#pragma unroll
    for (int mt = 0; mt < 2; mt++)
#pragma unroll
        for (int h = 0; h < 2; h++) {
            float srow = (float)(s0 + warp_m * 32 + mt * 16 + h * 8 + (lane >> 2));
            loc[mt][h] = (srow < mlen) ? (1.0f - srow / mlen) : 1.0f;
            rowsum[mt][h] = 0.f;
        }

    const int a_row = warp_m * 32 + (lane & 7) + ((lane >> 3) & 1) * 8;
    const int a_halfoff = (lane >> 4) * 16;
    const int b_row = warp_n * 32 + (lane & 7) + (lane >> 4) * 8;
    const int b_halfoff = ((lane >> 3) & 1) * 16;

    __syncthreads();

    // prologue: stages 0, 1
    stage_tiles(sc, 0, 0, 0);
    CP_COMMIT();
    stage_tiles(sc, 0, KC, 1);
    CP_COMMIT();

    for (int chunk = 0; chunk < NCHUNKS; chunk++) {
        const int nbase = chunk * NTILE;
        float acc[2][4][4];
        uint32_t acch[2][4][2];
#pragma unroll
        for (int mt = 0; mt < 2; mt++)
#pragma unroll
            for (int nt = 0; nt < 4; nt++) {
#pragma unroll
                for (int j = 0; j < 4; j++) acc[mt][nt][j] = 0.f;
                acch[mt][nt][0] = 0u;
                acch[mt][nt][1] = 0u;
            }

        for (int ks = 0; ks < KSTEPS; ks++) {
            // stage (chunk,ks) is complete when ≤1 newer group pending
            CP_WAIT1();
            __syncthreads();   // data visible to all warps; prior reads of this ring slot done

            // issue stage +2 ahead (always commit to keep group accounting exact)
            {
                int t2 = chunk * KSTEPS + ks + 2;
                if (t2 < NSTAGES) {
                    int c2 = t2 / KSTEPS, k2 = t2 - c2 * KSTEPS;
                    stage_tiles(sc, c2 * NTILE, k2 * KC, (ks + 2) % 3);
                }
                CP_COMMIT();
            }

            const uint32_t sb = sc.sbase + (ks % 3) * BUFSZ;
#pragma unroll
            for (int kk = 0; kk < 4; kk++) {
                const int kb = kk * 32;
                uint32_t ar[2][4], br[2][4];
#pragma unroll
                for (int mt = 0; mt < 2; mt++)
                    ldsm4(ar[mt][0], ar[mt][1], ar[mt][2], ar[mt][3],
                          sb + OFF_A + (a_row + mt * 16) * APAD + kb + a_halfoff);
#pragma unroll
                for (int nt2 = 0; nt2 < 2; nt2++)
                    ldsm4(br[nt2][0], br[nt2][1], br[nt2][2], br[nt2][3],
                          sb + OFF_B + (b_row + nt2 * 16) * APAD + kb + b_halfoff);
#pragma unroll
                for (int mt = 0; mt < 2; mt++)
#pragma unroll
                    for (int nt2 = 0; nt2 < 2; nt2++)
#pragma unroll
                        for (int s = 0; s < 2; s++)
                            mma16816h(acch[mt][nt2 * 2 + s], ar[mt][0], ar[mt][1], ar[mt][2],
                                      ar[mt][3], br[nt2][2 * s], br[nt2][2 * s + 1]);
            }

            // promote f16 partials to f32 every 3 ks (K=192 chain)
            if ((ks % 3) == 2) {
#pragma unroll
                for (int mt = 0; mt < 2; mt++)
#pragma unroll
                    for (int nt = 0; nt < 4; nt++) {
                        float2 p0 = __half22float2(*(__half2*)&acch[mt][nt][0]);
                        float2 p1 = __half22float2(*(__half2*)&acch[mt][nt][1]);
                        acc[mt][nt][0] += p0.x;
                        acc[mt][nt][1] += p0.y;
                        acc[mt][nt][2] += p1.x;
                        acc[mt][nt][3] += p1.y;
                        acch[mt][nt][0] = 0u;
                        acch[mt][nt][1] = 0u;
                    }
            }
        }

        // chunk epilogue: tanh (f16x2) + dot with w2 (register-only; no sync needed)
#pragma unroll
        for (int mt = 0; mt < 2; mt++) {
#pragma unroll
            for (int nt = 0; nt < 4; nt++) {
                const int c0 = nbase + warp_n * 32 + nt * 8 + (lane & 3) * 2;
                const float2 cx = *(const float2*)&sctx[c0];
                const float2 wv = *(const float2*)&sw2p[c0];
                {
                    float u0 = fmaf(loc[mt][0], acc[mt][nt][0], cx.x);
                    float u1 = fmaf(loc[mt][0], acc[mt][nt][1], cx.y);
                    __half2 hp = __floats2half2_rn(u0, u1);
                    uint32_t th = tanh2_f16(*(uint32_t*)&hp);
                    float2 tf = __half22float2(*(__half2*)&th);
                    rowsum[mt][0] = fmaf(tf.x, wv.x, fmaf(tf.y, wv.y, rowsum[mt][0]));
                }
                {
                    float u2 = fmaf(loc[mt][1], acc[mt][nt][2], cx.x);
                    float u3 = fmaf(loc[mt][1], acc[mt][nt][3], cx.y);
                    __half2 hp = __floats2half2_rn(u2, u3);
                    uint32_t th = tanh2_f16(*(uint32_t*)&hp);
                    float2 tf = __half22float2(*(__half2*)&th);
                    rowsum[mt][1] = fmaf(tf.x, wv.x, fmaf(tf.y, wv.y, rowsum[mt][1]));
                }
            }
        }
    }

    // reduce quad lanes, then across 4 warp_n via smem
    float* red = (float*)(smem + OFF_RED);
#pragma unroll
    for (int mt = 0; mt < 2; mt++)
#pragma unroll
        for (int h = 0; h < 2; h++) {
            float v = rowsum[mt][h];
            v += __shfl_xor_sync(0xffffffffu, v, 1);
            v += __shfl_xor_sync(0xffffffffu, v, 2);
            if ((lane & 3) == 0) {
                int lrow = warp_m * 32 + mt * 16 + h * 8 + (lane >> 2);
                red[lrow * 4 + warp_n] = v;
            }
        }
    __syncthreads();
    if (tid < MT)
        g_scores[b * NS + s0 + tid] =
            (red[tid * 4] + red[tid * 4 + 1]) + (red[tid * 4 + 2] + red[tid * 4 + 3]);
}

// ------------------------------------------------------------------
// v_ts + v_ns with inline softmax.  grid (6, 64) = 384 CTAs.
// ------------------------------------------------------------------
__global__ __launch_bounds__(512) void k_vts() {
    int b = blockIdx.y;
    int dc = blockIdx.x;
    int tid = threadIdx.x;
    __shared__ float sw[NS];
    __shared__ float red[512];
    __shared__ float sp[8][64][2];
    float mlen = g_mlen[b];

    float v = g_scores[b * NS + tid];
    red[tid] = v;
    __syncthreads();
    for (int o = 256; o > 0; o >>= 1) {
        if (tid < o) red[tid] = fmaxf(red[tid], red[tid + o]);
        __syncthreads();
    }
    float m = red[0];
    __syncthreads();
    float e = expf(v - m);
    red[tid] = e;
    __syncthreads();
    for (int o = 256; o > 0; o >>= 1) {
        if (tid < o) red[tid] += red[tid + o];
        __syncthreads();
    }
    float inv = 1.0f / red[0];
    float s = (float)tid;
    float l = (s < mlen) ? (1.0f - s / mlen) : 1.0f;
    sw[tid] = e * inv * l;
    __syncthreads();

    int sq = tid >> 6;
    int dd = tid & 63;
    int d = dc * 128 + dd * 2;
    const __half2* p = (const __half2*)(g_Ah + ((size_t)b * NS + sq * 64) * ND + d);
    float a0 = 0.f, a1 = 0.f;
#pragma unroll 8
    for (int s2 = 0; s2 < 64; s2++) {
        float2 h = __half22float2(p[(size_t)s2 * (ND / 2)]);
        float w = sw[sq * 64 + s2];
        a0 = fmaf(w, h.x, a0);
        a1 = fmaf(w, h.y, a1);
    }
    sp[sq][dd][0] = a0;
    sp[sq][dd][1] = a1;
    __syncthreads();
    if (sq == 0) {
        float t0 = 0.f, t1 = 0.f;
#pragma unroll
        for (int i = 0; i < 8; i++) {
            t0 += sp[i][dd][0];
            t1 += sp[i][dd][1];
        }
        g_vns[b * ND + d] = t0 + g_vs[b * ND + d];
        g_vns[b * ND + d + 1] = t1 + g_vs[b * ND + d + 1];
    }
}

// ------------------------------------------------------------------
// v_ms = tanh(v_ns @ Wm + bm)
// ------------------------------------------------------------------
__global__ __launch_bounds__(512) void k_vms(const float* __restrict__ Wm,
                                             const float* __restrict__ bm) {
    __shared__ float sp[4][128][2];
    int tid = threadIdx.x;
    int dt = tid & 127;
    int d = blockIdx.x * 128 + dt;
    int q = tid >> 7;
    int b0 = blockIdx.y * 2;
    const float* vb = g_vns + (size_t)b0 * ND;
    int k0 = q * 192;
    float a0 = 0.f, a1 = 0.f;
#pragma unroll 4
    for (int k = 0; k < 192; k++) {
        float w = Wm[(size_t)(k0 + k) * ND + d];
        a0 = fmaf(vb[k0 + k], w, a0);
        a1 = fmaf(vb[ND + k0 + k], w, a1);
    }
    sp[q][dt][0] = a0;
    sp[q][dt][1] = a1;
    __syncthreads();
    if (q == 0) {
        float bb = bm[d];
#pragma unroll
        for (int i = 0; i < 2; i++) {
            float s = sp[0][dt][i] + sp[1][dt][i] + sp[2][dt][i] + sp[3][dt][i] + bb;
            g_vms[(b0 + i) * ND + d] = tanhf(s);
        }
    }
}

// ------------------------------------------------------------------
// logits: 64 CTAs (one per b), 256 thr, smem tree reduce
// ------------------------------------------------------------------
__global__ __launch_bounds__(256) void k_logits(const float* __restrict__ Wd,
                                                const float* __restrict__ bd,
                                                float* __restrict__ out) {
    int b = blockIdx.x;
    int tid = threadIdx.x;
    __shared__ float red[256][3];
    float a0 = 0.f, a1 = 0.f, a2 = 0.f;
    const float* v = g_vms + b * ND;
    for (int d = tid; d < ND; d += 256) {
        float vv = v[d];
        a0 = fmaf(vv, Wd[d * 3 + 0], a0);
        a1 = fmaf(vv, Wd[d * 3 + 1], a1);
        a2 = fmaf(vv, Wd[d * 3 + 2], a2);
    }
    red[tid][0] = a0;
    red[tid][1] = a1;
    red[tid][2] = a2;
    __syncthreads();
    for (int o = 128; o > 0; o >>= 1) {
        if (tid < o) {
            red[tid][0] += red[tid + o][0];
            red[tid][1] += red[tid + o][1];
            red[tid][2] += red[tid + o][2];
        }
        __syncthreads();
    }
    if (tid < 3)
        out[b * 3 + tid] = red[0][tid] + bd[tid];
}

// ------------------------------------------------------------------
// launch  (7 launches; k_null makes k_scores the 4th -> ncu capture)
// ------------------------------------------------------------------
extern "C" void kernel_launch(void* const* d_in, const int* in_sizes, int n_in,
                              void* d_out, int out_size) {
    (void)in_sizes; (void)n_in; (void)out_size;
    const float* mem  = (const float*)d_in[0];
    const float* asp  = (const float*)d_in[1];
    const int* ids    = (const int*)d_in[2];
    const int* tids   = (const int*)d_in[3];
    const float* W1 = (const float*)d_in[4];
    const float* b1 = (const float*)d_in[5];
    const float* w2 = (const float*)d_in[6];
    const float* Wm = (const float*)d_in[7];
    const float* bm = (const float*)d_in[8];
    const float* Wd = (const float*)d_in[9];
    const float* bd = (const float*)d_in[10];
    float* out = (float*)d_out;

    cudaFuncSetAttribute(k_scores, cudaFuncAttributeMaxDynamicSharedMemorySize, SMEMSZ);

    k_head<<<1312, 512>>>(mem, asp, ids, tids, W1);
    k_ctx<<<dim3(ND / 128, NB / 2), 512>>>(b1);
    k_null<<<1, 32>>>();
    k_scores<<<dim3(NS / MT, NB), 512, SMEMSZ>>>(w2);
    k_vts<<<dim3(6, NB), 512>>>();
    k_vms<<<dim3(ND / 128, NB / 2), 512>>>(Wm, bm);
    k_logits<<<NB, 256>>>(Wd, bd, out);
}

// round 16
// speedup vs baseline: 1.1487x; 1.0880x over previous
#include <cuda_runtime.h>
#include <cuda_fp16.h>
#include <cstdint>

#define NB 64
#define NS 512
#define NTA 8
#define ND 768

// ------------------------------------------------------------------
// scratch (static __device__; no allocations allowed)
// ------------------------------------------------------------------
__device__ float g_mlen[NB], g_alen[NB];
__device__ float g_va[NB * ND], g_vs[NB * ND], g_ctx[NB * ND];
__device__ float g_scores[NB * NS];
__device__ float g_vns[NB * ND], g_vms[NB * ND];

// fp16 operands
__device__ __half g_Ah[(size_t)NB * NS * ND];
__device__ __half g_Bh[(size_t)ND * ND];      // [n][k] = W1_m[k][n]
__device__ __half g_Wch[(size_t)2 * ND * ND]; // W1_a, W1_s in [k][d] (fp16)

// ------------------------------------------------------------------
// PTX helpers (baseline ISA only)
// ------------------------------------------------------------------
__device__ __forceinline__ uint32_t smem_u32(const void* p) {
    uint32_t a;
    asm("{ .reg .u64 t; cvta.to.shared.u64 t, %1; cvt.u32.u64 %0, t; }" : "=r"(a) : "l"(p));
    return a;
}
__device__ __forceinline__ void cp16(uint32_t dst, const void* src) {
    asm volatile("cp.async.cg.shared.global [%0], [%1], 16;" :: "r"(dst), "l"(src));
}
#define CP_COMMIT() asm volatile("cp.async.commit_group;" ::: "memory")
#define CP_WAIT1()  asm volatile("cp.async.wait_group 1;" ::: "memory")
#define CP_WAIT0()  asm volatile("cp.async.wait_group 0;" ::: "memory")

__device__ __forceinline__ void ldsm4(uint32_t& r0, uint32_t& r1, uint32_t& r2, uint32_t& r3,
                                      uint32_t addr) {
    asm volatile("ldmatrix.sync.aligned.m8n8.x4.shared.b16 {%0,%1,%2,%3}, [%4];"
                 : "=r"(r0), "=r"(r1), "=r"(r2), "=r"(r3) : "r"(addr));
}
// f32-accumulate MMA
__device__ __forceinline__ void mma16816(float* c, uint32_t a0, uint32_t a1, uint32_t a2,
                                         uint32_t a3, uint32_t b0, uint32_t b1) {
    asm volatile(
        "mma.sync.aligned.m16n8k16.row.col.f32.f16.f16.f32 "
        "{%0,%1,%2,%3}, {%4,%5,%6,%7}, {%8,%9}, {%0,%1,%2,%3};"
        : "+f"(c[0]), "+f"(c[1]), "+f"(c[2]), "+f"(c[3])
        : "r"(a0), "r"(a1), "r"(a2), "r"(a3), "r"(b0), "r"(b1));
}
__device__ __forceinline__ uint32_t tanh2_f16(uint32_t x) {
    uint32_t y;
    asm("tanh.approx.f16x2 %0, %1;" : "=r"(y) : "r"(x));
    return y;
}

// ------------------------------------------------------------------
// k_head: means+convert / W1_m transpose / lens / W1_a,W1_s fp16 convert
// ------------------------------------------------------------------
__global__ __launch_bounds__(512) void k_head(const float* __restrict__ mem,
                                              const float* __restrict__ asp,
                                              const int* __restrict__ ids,
                                              const int* __restrict__ tids,
                                              const float* __restrict__ W1) {
    int blk = blockIdx.x;
    int tid = threadIdx.x;
    if (blk < 384) {
        int b = blk / 6;
        int db = blk % 6;
        __shared__ float sp[4][128];
        __shared__ float s_ml, s_al;
        float* red = &sp[0][0];
        red[tid] = (ids[b * NS + tid] != 0) ? 1.0f : 0.0f;
        __syncthreads();
        for (int o = 256; o > 0; o >>= 1) {
            if (tid < o) red[tid] += red[tid + o];
            __syncthreads();
        }
        if (tid == 0) {
            s_ml = fmaxf(red[0], 1.0f);
            int a = 0;
#pragma unroll
            for (int t = 0; t < NTA; t++) a += (tids[b * NTA + t] != 0);
            s_al = fmaxf((float)a, 1.0f);
        }
        __syncthreads();
        float mlen = s_ml, alen = s_al;
        __syncthreads();
        int d = db * 128 + (tid & 127);
        int q = tid >> 7;
        float acc = 0.f;
        const float* p = mem + ((size_t)b * NS + q * 128) * ND + d;
        __half* ah = g_Ah + ((size_t)b * NS + q * 128) * ND + d;
#pragma unroll 8
        for (int s = 0; s < 128; s++) {
            float v = p[(size_t)s * ND];
            acc += v;
            ah[(size_t)s * ND] = __float2half_rn(v);
        }
        sp[q][tid & 127] = acc;
        __syncthreads();
        if (q == 0) {
            float tot = sp[0][tid] + sp[1][tid] + sp[2][tid] + sp[3][tid];
            g_vs[b * ND + d] = tot / mlen;
            float a = 0.f;
            const float* ap = asp + ((size_t)b * NTA) * ND + d;
#pragma unroll
            for (int t = 0; t < NTA; t++) a += ap[(size_t)t * ND];
            g_va[b * ND + d] = a / alen;
        }
    } else if (blk < 960) {
        __shared__ float t[32][33];
        int bb = blk - 384;
        int k0 = (bb % 24) * 32, n0 = (bb / 24) * 32;
        int tx = tid & 31, ty = tid >> 5;
        for (int i = ty; i < 32; i += 16)
            t[i][tx] = W1[(size_t)(k0 + i) * ND + n0 + tx];
        __syncthreads();
        for (int i = ty; i < 32; i += 16)
            g_Bh[(size_t)(n0 + i) * ND + k0 + tx] = __float2half_rn(t[tx][i]);
    } else if (blk < 1024) {
        int b = blk - 960;
        __shared__ float red[512];
        red[tid] = (ids[b * NS + tid] != 0) ? 1.0f : 0.0f;
        __syncthreads();
        for (int o = 256; o > 0; o >>= 1) {
            if (tid < o) red[tid] += red[tid + o];
            __syncthreads();
        }
        if (tid == 0) {
            g_mlen[b] = fmaxf(red[0], 1.0f);
            int a = 0;
#pragma unroll
            for (int t = 0; t < NTA; t++) a += (tids[b * NTA + t] != 0);
            g_alen[b] = fmaxf((float)a, 1.0f);
        }
    } else {
        size_t base = (size_t)(blk - 1024) * 4096 + (size_t)tid * 8;
        const float* src = W1 + (size_t)ND * ND + base;
        float4 v0 = *(const float4*)src;
        float4 v1 = *(const float4*)(src + 4);
        __half h[8];
        h[0] = __float2half_rn(v0.x); h[1] = __float2half_rn(v0.y);
        h[2] = __float2half_rn(v0.z); h[3] = __float2half_rn(v0.w);
        h[4] = __float2half_rn(v1.x); h[5] = __float2half_rn(v1.y);
        h[6] = __float2half_rn(v1.z); h[7] = __float2half_rn(v1.w);
        *(uint4*)(g_Wch + base) = *(uint4*)h;
    }
}

// ------------------------------------------------------------------
// ctx = v_a @ W1_a + v_s @ W1_s + b1   (fp16 weights)
// ------------------------------------------------------------------
__global__ __launch_bounds__(512) void k_ctx(const float* __restrict__ b1) {
    __shared__ float sp[4][128][2];
    int tid = threadIdx.x;
    int dt = tid & 127;
    int d = blockIdx.x * 128 + dt;
    int q = tid >> 7;
    int b0 = blockIdx.y * 2;
    const __half* W = g_Wch + (size_t)(q >> 1) * ND * ND + d;
    const float* vb = ((q >> 1) ? g_vs : g_va) + (size_t)b0 * ND;
    int k0 = (q & 1) * 384;
    float a0 = 0.f, a1 = 0.f;
#pragma unroll 4
    for (int k = 0; k < 384; k++) {
        float w = __half2float(W[(size_t)(k0 + k) * ND]);
        a0 = fmaf(vb[k0 + k], w, a0);
        a1 = fmaf(vb[ND + k0 + k], w, a1);
    }
    sp[q][dt][0] = a0;
    sp[q][dt][1] = a1;
    __syncthreads();
    if (q == 0) {
        float bb = b1[d];
#pragma unroll
        for (int i = 0; i < 2; i++) {
            float s = sp[0][dt][i] + sp[1][dt][i] + sp[2][dt][i] + sp[3][dt][i] + bb;
            g_ctx[(b0 + i) * ND + d] = s;
        }
    }
}

// ------------------------------------------------------------------
// null kernel: makes k_scores the 4th launch (ncu capture target)
// ------------------------------------------------------------------
__global__ void k_null() {}

// ------------------------------------------------------------------
// fused scores: f32-acc mma.sync, 256 thr, 2 CTA/SM  [R10 form, 134us]
// ------------------------------------------------------------------
#define MT 128
#define NTILE 128
#define KC 64
#define NCHUNKS (ND / NTILE)   // 6
#define KSTEPS (ND / KC)       // 12
#define APAD 144

#define OFF_A 0
#define OFF_B 18432
#define BUFSZ 36864
#define OFF_CTX (2 * BUFSZ)          // 73728
#define OFF_W2  (OFF_CTX + 3072)     // 76800
#define OFF_RED (OFF_W2 + 3072)      // 79872
#define SMEMSZ  (OFF_RED + 1024)     // 80896

struct ScoreCtx {
    const __half* gA;
    uint32_t sbase;
};

__device__ __forceinline__ void stage_tiles(const ScoreCtx& sc, int nbase, int k0, int buf) {
    int tid = threadIdx.x;
    uint32_t sb = sc.sbase + buf * BUFSZ;
#pragma unroll
    for (int t = 0; t < 4; t++) {
        int i = tid + t * 256;
        int r = i >> 3, c = i & 7;
        uint32_t d = sb + r * APAD + c * 16;
        cp16(d + OFF_A, sc.gA + (size_t)r * ND + k0 + c * 8);
        cp16(d + OFF_B, g_Bh + (size_t)(nbase + r) * ND + k0 + c * 8);
    }
}

__global__ void __launch_bounds__(256, 2) k_scores(const float* __restrict__ w2) {
    extern __shared__ char smem[];
    const int tid = threadIdx.x;
    const int b = blockIdx.y;
    const int s0 = blockIdx.x * MT;
    const int lane = tid & 31, wid = tid >> 5;
    const int warp_m = wid & 3, warp_n = wid >> 2;   // 4 m-warps x 2 n-warps

    float* sctx = (float*)(smem + OFF_CTX);
    float* sw2p = (float*)(smem + OFF_W2);
    for (int i = tid; i < ND; i += 256) {
        sctx[i] = g_ctx[b * ND + i];
        sw2p[i] = w2[i];
    }

    ScoreCtx sc;
    sc.gA = g_Ah + ((size_t)b * NS + s0) * ND;
    sc.sbase = smem_u32(smem);

    const float mlen = g_mlen[b];
    float loc[2][2], rowsum[2][2];
#pragma unroll
    for (int mt = 0; mt < 2; mt++)
#pragma unroll
        for (int h = 0; h < 2; h++) {
            float srow = (float)(s0 + warp_m * 32 + mt * 16 + h * 8 + (lane >> 2));
            loc[mt][h] = (srow < mlen) ? (1.0f - srow / mlen) : 1.0f;
            rowsum[mt][h] = 0.f;
        }

    const int a_row = warp_m * 32 + (lane & 7) + ((lane >> 3) & 1) * 8;
    const int a_halfoff = (lane >> 4) * 16;
    const int b_row = warp_n * 64 + (lane & 7) + (lane >> 4) * 8;
    const int b_halfoff = ((lane >> 3) & 1) * 16;

    __syncthreads();

    stage_tiles(sc, 0, 0, 0);
    CP_COMMIT();

    for (int chunk = 0; chunk < NCHUNKS; chunk++) {
        const int nbase = chunk * NTILE;
        float acc[2][8][4];
#pragma unroll
        for (int mt = 0; mt < 2; mt++)
#pragma unroll
            for (int nt = 0; nt < 8; nt++)
#pragma unroll
                for (int j = 0; j < 4; j++) acc[mt][nt][j] = 0.f;

        for (int ks = 0; ks < KSTEPS; ks++) {
            const int buf = ks & 1;
            if (ks + 1 < KSTEPS) {
                stage_tiles(sc, nbase, (ks + 1) * KC, buf ^ 1);
                CP_COMMIT();
                CP_WAIT1();
            } else {
                CP_WAIT0();
            }
            __syncthreads();

            const uint32_t sb = sc.sbase + buf * BUFSZ;
#pragma unroll
            for (int kk = 0; kk < 4; kk++) {
                const int kb = kk * 32;
                uint32_t ar[2][4], br[4][4];
#pragma unroll
                for (int mt = 0; mt < 2; mt++)
                    ldsm4(ar[mt][0], ar[mt][1], ar[mt][2], ar[mt][3],
                          sb + OFF_A + (a_row + mt * 16) * APAD + kb + a_halfoff);
#pragma unroll
                for (int nt2 = 0; nt2 < 4; nt2++)
                    ldsm4(br[nt2][0], br[nt2][1], br[nt2][2], br[nt2][3],
                          sb + OFF_B + (b_row + nt2 * 16) * APAD + kb + b_halfoff);
#pragma unroll
                for (int mt = 0; mt < 2; mt++)
#pragma unroll
                    for (int nt2 = 0; nt2 < 4; nt2++)
#pragma unroll
                        for (int s = 0; s < 2; s++)
                            mma16816(acc[mt][nt2 * 2 + s], ar[mt][0], ar[mt][1], ar[mt][2],
                                     ar[mt][3], br[nt2][2 * s], br[nt2][2 * s + 1]);
            }
            __syncthreads();
        }

        if (chunk + 1 < NCHUNKS) {
            stage_tiles(sc, nbase + NTILE, 0, 0);
            CP_COMMIT();
        }

        // epilogue: tanh (f16x2) + dot with w2
#pragma unroll
        for (int mt = 0; mt < 2; mt++) {
#pragma unroll
            for (int nt = 0; nt < 8; nt++) {
                const int c0 = nbase + warp_n * 64 + nt * 8 + (lane & 3) * 2;
                const float2 cx = *(const float2*)&sctx[c0];
                const float2 wv = *(const float2*)&sw2p[c0];
                {
                    float u0 = fmaf(loc[mt][0], acc[mt][nt][0], cx.x);
                    float u1 = fmaf(loc[mt][0], acc[mt][nt][1], cx.y);
                    __half2 hp = __floats2half2_rn(u0, u1);
                    uint32_t th = tanh2_f16(*(uint32_t*)&hp);
                    float2 tf = __half22float2(*(__half2*)&th);
                    rowsum[mt][0] = fmaf(tf.x, wv.x, fmaf(tf.y, wv.y, rowsum[mt][0]));
                }
                {
                    float u2 = fmaf(loc[mt][1], acc[mt][nt][2], cx.x);
                    float u3 = fmaf(loc[mt][1], acc[mt][nt][3], cx.y);
                    __half2 hp = __floats2half2_rn(u2, u3);
                    uint32_t th = tanh2_f16(*(uint32_t*)&hp);
                    float2 tf = __half22float2(*(__half2*)&th);
                    rowsum[mt][1] = fmaf(tf.x, wv.x, fmaf(tf.y, wv.y, rowsum[mt][1]));
                }
            }
        }
    }

    // reduce quad lanes, then across warp_n via smem
    float* red = (float*)(smem + OFF_RED);
#pragma unroll
    for (int mt = 0; mt < 2; mt++)
#pragma unroll
        for (int h = 0; h < 2; h++) {
            float v = rowsum[mt][h];
            v += __shfl_xor_sync(0xffffffffu, v, 1);
            v += __shfl_xor_sync(0xffffffffu, v, 2);
            if ((lane & 3) == 0) {
                int lrow = warp_m * 32 + mt * 16 + h * 8 + (lane >> 2);
                red[lrow * 2 + warp_n] = v;
            }
        }
    __syncthreads();
    if (tid < MT)
        g_scores[b * NS + s0 + tid] = red[tid * 2] + red[tid * 2 + 1];
}

// ------------------------------------------------------------------
// v_ts + v_ns with inline softmax.  grid (6, 64) = 384 CTAs.
// ------------------------------------------------------------------
__global__ __launch_bounds__(512) void k_vts() {
    int b = blockIdx.y;
    int dc = blockIdx.x;
    int tid = threadIdx.x;
    __shared__ float sw[NS];
    __shared__ float red[512];
    __shared__ float sp[8][64][2];
    float mlen = g_mlen[b];

    float v = g_scores[b * NS + tid];
    red[tid] = v;
    __syncthreads();
    for (int o = 256; o > 0; o >>= 1) {
        if (tid < o) red[tid] = fmaxf(red[tid], red[tid + o]);
        __syncthreads();
    }
    float m = red[0];
    __syncthreads();
    float e = expf(v - m);
    red[tid] = e;
    __syncthreads();
    for (int o = 256; o > 0; o >>= 1) {
        if (tid < o) red[tid] += red[tid + o];
        __syncthreads();
    }
    float inv = 1.0f / red[0];
    float s = (float)tid;
    float l = (s < mlen) ? (1.0f - s / mlen) : 1.0f;
    sw[tid] = e * inv * l;
    __syncthreads();

    int sq = tid >> 6;
    int dd = tid & 63;
    int d = dc * 128 + dd * 2;
    const __half2* p = (const __half2*)(g_Ah + ((size_t)b * NS + sq * 64) * ND + d);
    float a0 = 0.f, a1 = 0.f;
#pragma unroll 8
    for (int s2 = 0; s2 < 64; s2++) {
        float2 h = __half22float2(p[(size_t)s2 * (ND / 2)]);
        float w = sw[sq * 64 + s2];
        a0 = fmaf(w, h.x, a0);
        a1 = fmaf(w, h.y, a1);
    }
    sp[sq][dd][0] = a0;
    sp[sq][dd][1] = a1;
    __syncthreads();
    if (sq == 0) {
        float t0 = 0.f, t1 = 0.f;
#pragma unroll
        for (int i = 0; i < 8; i++) {
            t0 += sp[i][dd][0];
            t1 += sp[i][dd][1];
        }
        g_vns[b * ND + d] = t0 + g_vs[b * ND + d];
        g_vns[b * ND + d + 1] = t1 + g_vs[b * ND + d + 1];
    }
}

// ------------------------------------------------------------------
// v_ms = tanh(v_ns @ Wm + bm)
// ------------------------------------------------------------------
__global__ __launch_bounds__(512) void k_vms(const float* __restrict__ Wm,
                                             const float* __restrict__ bm) {
    __shared__ float sp[4][128][2];
    int tid = threadIdx.x;
    int dt = tid & 127;
    int d = blockIdx.x * 128 + dt;
    int q = tid >> 7;
    int b0 = blockIdx.y * 2;
    const float* vb = g_vns + (size_t)b0 * ND;
    int k0 = q * 192;
    float a0 = 0.f, a1 = 0.f;
#pragma unroll 4
    for (int k = 0; k < 192; k++) {
        float w = Wm[(size_t)(k0 + k) * ND + d];
        a0 = fmaf(vb[k0 + k], w, a0);
        a1 = fmaf(vb[ND + k0 + k], w, a1);
    }
    sp[q][dt][0] = a0;
    sp[q][dt][1] = a1;
    __syncthreads();
    if (q == 0) {
        float bb = bm[d];
#pragma unroll
        for (int i = 0; i < 2; i++) {
            float s = sp[0][dt][i] + sp[1][dt][i] + sp[2][dt][i] + sp[3][dt][i] + bb;
            g_vms[(b0 + i) * ND + d] = tanhf(s);
        }
    }
}

// ------------------------------------------------------------------
// logits: 64 CTAs (one per b), 256 thr, smem tree reduce
// ------------------------------------------------------------------
__global__ __launch_bounds__(256) void k_logits(const float* __restrict__ Wd,
                                                const float* __restrict__ bd,
                                                float* __restrict__ out) {
    int b = blockIdx.x;
    int tid = threadIdx.x;
    __shared__ float red[256][3];
    float a0 = 0.f, a1 = 0.f, a2 = 0.f;
    const float* v = g_vms + b * ND;
    for (int d = tid; d < ND; d += 256) {
        float vv = v[d];
        a0 = fmaf(vv, Wd[d * 3 + 0], a0);
        a1 = fmaf(vv, Wd[d * 3 + 1], a1);
        a2 = fmaf(vv, Wd[d * 3 + 2], a2);
    }
    red[tid][0] = a0;
    red[tid][1] = a1;
    red[tid][2] = a2;
    __syncthreads();
    for (int o = 128; o > 0; o >>= 1) {
        if (tid < o) {
            red[tid][0] += red[tid + o][0];
            red[tid][1] += red[tid + o][1];
            red[tid][2] += red[tid + o][2];
        }
        __syncthreads();
    }
    if (tid < 3)
        out[b * 3 + tid] = red[0][tid] + bd[tid];
}

// ------------------------------------------------------------------
// launch  (7 launches; k_null makes k_scores the 4th -> ncu capture)
// ------------------------------------------------------------------
extern "C" void kernel_launch(void* const* d_in, const int* in_sizes, int n_in,
                              void* d_out, int out_size) {
    (void)in_sizes; (void)n_in; (void)out_size;
    const float* mem  = (const float*)d_in[0];
    const float* asp  = (const float*)d_in[1];
    const int* ids    = (const int*)d_in[2];
    const int* tids   = (const int*)d_in[3];
    const float* W1 = (const float*)d_in[4];
    const float* b1 = (const float*)d_in[5];
    const float* w2 = (const float*)d_in[6];
    const float* Wm = (const float*)d_in[7];
    const float* bm = (const float*)d_in[8];
    const float* Wd = (const float*)d_in[9];
    const float* bd = (const float*)d_in[10];
    float* out = (float*)d_out;

    cudaFuncSetAttribute(k_scores, cudaFuncAttributeMaxDynamicSharedMemorySize, SMEMSZ);

    k_head<<<1312, 512>>>(mem, asp, ids, tids, W1);
    k_ctx<<<dim3(ND / 128, NB / 2), 512>>>(b1);
    k_null<<<1, 32>>>();
    k_scores<<<dim3(NS / MT, NB), 256, SMEMSZ>>>(w2);
    k_vts<<<dim3(6, NB), 512>>>();
    k_vms<<<dim3(ND / 128, NB / 2), 512>>>(Wm, bm);
    k_logits<<<NB, 256>>>(Wd, bd, out);
}

// round 17
// speedup vs baseline: 1.1661x; 1.0152x over previous
#include <cuda_runtime.h>
#include <cuda_fp16.h>
#include <cstdint>

#define NB 64
#define NS 512
#define NTA 8
#define ND 768

// ------------------------------------------------------------------
// scratch (static __device__; no allocations allowed)
// ------------------------------------------------------------------
__device__ float g_mlen[NB], g_alen[NB];
__device__ float g_va[NB * ND], g_vs[NB * ND], g_ctx[NB * ND];
__device__ float g_scores[NB * NS];
__device__ float g_vns[NB * ND], g_vms[NB * ND];

// fp16 operands
__device__ __half g_Ah[(size_t)NB * NS * ND];
__device__ __half g_Bh[(size_t)ND * ND];      // [n][k] = W1_m[k][n]
__device__ __half g_Wch[(size_t)2 * ND * ND]; // W1_a, W1_s in [k][d] (fp16)
__device__ __half g_Wmh[(size_t)ND * ND];     // Wm in [k][d] (fp16)

// ------------------------------------------------------------------
// PTX helpers (baseline ISA only)
// ------------------------------------------------------------------
__device__ __forceinline__ uint32_t smem_u32(const void* p) {
    uint32_t a;
    asm("{ .reg .u64 t; cvta.to.shared.u64 t, %1; cvt.u32.u64 %0, t; }" : "=r"(a) : "l"(p));
    return a;
}
__device__ __forceinline__ void cp16(uint32_t dst, const void* src) {
    asm volatile("cp.async.cg.shared.global [%0], [%1], 16;" :: "r"(dst), "l"(src));
}
#define CP_COMMIT() asm volatile("cp.async.commit_group;" ::: "memory")
#define CP_WAIT1()  asm volatile("cp.async.wait_group 1;" ::: "memory")
#define CP_WAIT0()  asm volatile("cp.async.wait_group 0;" ::: "memory")

__device__ __forceinline__ void ldsm4(uint32_t& r0, uint32_t& r1, uint32_t& r2, uint32_t& r3,
                                      uint32_t addr) {
    asm volatile("ldmatrix.sync.aligned.m8n8.x4.shared.b16 {%0,%1,%2,%3}, [%4];"
                 : "=r"(r0), "=r"(r1), "=r"(r2), "=r"(r3) : "r"(addr));
}
// f32-accumulate MMA
__device__ __forceinline__ void mma16816(float* c, uint32_t a0, uint32_t a1, uint32_t a2,
                                         uint32_t a3, uint32_t b0, uint32_t b1) {
    asm volatile(
        "mma.sync.aligned.m16n8k16.row.col.f32.f16.f16.f32 "
        "{%0,%1,%2,%3}, {%4,%5,%6,%7}, {%8,%9}, {%0,%1,%2,%3};"
        : "+f"(c[0]), "+f"(c[1]), "+f"(c[2]), "+f"(c[3])
        : "r"(a0), "r"(a1), "r"(a2), "r"(a3), "r"(b0), "r"(b1));
}
__device__ __forceinline__ uint32_t tanh2_f16(uint32_t x) {
    uint32_t y;
    asm("tanh.approx.f16x2 %0, %1;" : "=r"(y) : "r"(x));
    return y;
}

// ------------------------------------------------------------------
// k_head: means+convert / W1_m transpose / lens / W1_a,W1_s convert / Wm convert
//   [0,384): means (b, d-block) + fp16 convert of memory
//   [384,960): W1_m transpose+fp16 (24x24 tiles)
//   [960,1024): global lens
//   [1024,1312): fp16 convert of W1_a,W1_s
//   [1312,1456): fp16 convert of Wm
// ------------------------------------------------------------------
__global__ __launch_bounds__(512) void k_head(const float* __restrict__ mem,
                                              const float* __restrict__ asp,
                                              const int* __restrict__ ids,
                                              const int* __restrict__ tids,
                                              const float* __restrict__ W1,
                                              const float* __restrict__ Wm) {
    int blk = blockIdx.x;
    int tid = threadIdx.x;
    if (blk < 384) {
        int b = blk / 6;
        int db = blk % 6;
        __shared__ float sp[4][128];
        __shared__ float s_ml, s_al;
        float* red = &sp[0][0];
        red[tid] = (ids[b * NS + tid] != 0) ? 1.0f : 0.0f;
        __syncthreads();
        for (int o = 256; o > 0; o >>= 1) {
            if (tid < o) red[tid] += red[tid + o];
            __syncthreads();
        }
        if (tid == 0) {
            s_ml = fmaxf(red[0], 1.0f);
            int a = 0;
#pragma unroll
            for (int t = 0; t < NTA; t++) a += (tids[b * NTA + t] != 0);
            s_al = fmaxf((float)a, 1.0f);
        }
        __syncthreads();
        float mlen = s_ml, alen = s_al;
        __syncthreads();
        int d = db * 128 + (tid & 127);
        int q = tid >> 7;
        float acc = 0.f;
        const float* p = mem + ((size_t)b * NS + q * 128) * ND + d;
        __half* ah = g_Ah + ((size_t)b * NS + q * 128) * ND + d;
#pragma unroll 8
        for (int s = 0; s < 128; s++) {
            float v = p[(size_t)s * ND];
            acc += v;
            ah[(size_t)s * ND] = __float2half_rn(v);
        }
        sp[q][tid & 127] = acc;
        __syncthreads();
        if (q == 0) {
            float tot = sp[0][tid] + sp[1][tid] + sp[2][tid] + sp[3][tid];
            g_vs[b * ND + d] = tot / mlen;
            float a = 0.f;
            const float* ap = asp + ((size_t)b * NTA) * ND + d;
#pragma unroll
            for (int t = 0; t < NTA; t++) a += ap[(size_t)t * ND];
            g_va[b * ND + d] = a / alen;
        }
    } else if (blk < 960) {
        __shared__ float t[32][33];
        int bb = blk - 384;
        int k0 = (bb % 24) * 32, n0 = (bb / 24) * 32;
        int tx = tid & 31, ty = tid >> 5;
        for (int i = ty; i < 32; i += 16)
            t[i][tx] = W1[(size_t)(k0 + i) * ND + n0 + tx];
        __syncthreads();
        for (int i = ty; i < 32; i += 16)
            g_Bh[(size_t)(n0 + i) * ND + k0 + tx] = __float2half_rn(t[tx][i]);
    } else if (blk < 1024) {
        int b = blk - 960;
        __shared__ float red[512];
        red[tid] = (ids[b * NS + tid] != 0) ? 1.0f : 0.0f;
        __syncthreads();
        for (int o = 256; o > 0; o >>= 1) {
            if (tid < o) red[tid] += red[tid + o];
            __syncthreads();
        }
        if (tid == 0) {
            g_mlen[b] = fmaxf(red[0], 1.0f);
            int a = 0;
#pragma unroll
            for (int t = 0; t < NTA; t++) a += (tids[b * NTA + t] != 0);
            g_alen[b] = fmaxf((float)a, 1.0f);
        }
    } else if (blk < 1312) {
        size_t base = (size_t)(blk - 1024) * 4096 + (size_t)tid * 8;
        const float* src = W1 + (size_t)ND * ND + base;
        float4 v0 = *(const float4*)src;
        float4 v1 = *(const float4*)(src + 4);
        __half h[8];
        h[0] = __float2half_rn(v0.x); h[1] = __float2half_rn(v0.y);
        h[2] = __float2half_rn(v0.z); h[3] = __float2half_rn(v0.w);
        h[4] = __float2half_rn(v1.x); h[5] = __float2half_rn(v1.y);
        h[6] = __float2half_rn(v1.z); h[7] = __float2half_rn(v1.w);
        *(uint4*)(g_Wch + base) = *(uint4*)h;
    } else {
        size_t base = (size_t)(blk - 1312) * 4096 + (size_t)tid * 8;
        const float* src = Wm + base;
        float4 v0 = *(const float4*)src;
        float4 v1 = *(const float4*)(src + 4);
        __half h[8];
        h[0] = __float2half_rn(v0.x); h[1] = __float2half_rn(v0.y);
        h[2] = __float2half_rn(v0.z); h[3] = __float2half_rn(v0.w);
        h[4] = __float2half_rn(v1.x); h[5] = __float2half_rn(v1.y);
        h[6] = __float2half_rn(v1.z); h[7] = __float2half_rn(v1.w);
        *(uint4*)(g_Wmh + base) = *(uint4*)h;
    }
}

// ------------------------------------------------------------------
// ctx = v_a @ W1_a + v_s @ W1_s + b1   (fp16 weights)
// ------------------------------------------------------------------
__global__ __launch_bounds__(512) void k_ctx(const float* __restrict__ b1) {
    __shared__ float sp[4][128][2];
    int tid = threadIdx.x;
    int dt = tid & 127;
    int d = blockIdx.x * 128 + dt;
    int q = tid >> 7;
    int b0 = blockIdx.y * 2;
    const __half* W = g_Wch + (size_t)(q >> 1) * ND * ND + d;
    const float* vb = ((q >> 1) ? g_vs : g_va) + (size_t)b0 * ND;
    int k0 = (q & 1) * 384;
    float a0 = 0.f, a1 = 0.f;
#pragma unroll 4
    for (int k = 0; k < 384; k++) {
        float w = __half2float(W[(size_t)(k0 + k) * ND]);
        a0 = fmaf(vb[k0 + k], w, a0);
        a1 = fmaf(vb[ND + k0 + k], w, a1);
    }
    sp[q][dt][0] = a0;
    sp[q][dt][1] = a1;
    __syncthreads();
    if (q == 0) {
        float bb = b1[d];
#pragma unroll
        for (int i = 0; i < 2; i++) {
            float s = sp[0][dt][i] + sp[1][dt][i] + sp[2][dt][i] + sp[3][dt][i] + bb;
            g_ctx[(b0 + i) * ND + d] = s;
        }
    }
}

// ------------------------------------------------------------------
// fused scores: f32-acc mma.sync, 256 thr, 2 CTA/SM  [at HMMA rt16 floor]
// ------------------------------------------------------------------
#define MT 128
#define NTILE 128
#define KC 64
#define NCHUNKS (ND / NTILE)   // 6
#define KSTEPS (ND / KC)       // 12
#define APAD 144

#define OFF_A 0
#define OFF_B 18432
#define BUFSZ 36864
#define OFF_CTX (2 * BUFSZ)          // 73728
#define OFF_W2  (OFF_CTX + 3072)     // 76800
#define OFF_RED (OFF_W2 + 3072)      // 79872
#define SMEMSZ  (OFF_RED + 1024)     // 80896

struct ScoreCtx {
    const __half* gA;
    uint32_t sbase;
};

__device__ __forceinline__ void stage_tiles(const ScoreCtx& sc, int nbase, int k0, int buf) {
    int tid = threadIdx.x;
    uint32_t sb = sc.sbase + buf * BUFSZ;
#pragma unroll
    for (int t = 0; t < 4; t++) {
        int i = tid + t * 256;
        int r = i >> 3, c = i & 7;
        uint32_t d = sb + r * APAD + c * 16;
        cp16(d + OFF_A, sc.gA + (size_t)r * ND + k0 + c * 8);
        cp16(d + OFF_B, g_Bh + (size_t)(nbase + r) * ND + k0 + c * 8);
    }
}

__global__ void __launch_bounds__(256, 2) k_scores(const float* __restrict__ w2) {
    extern __shared__ char smem[];
    const int tid = threadIdx.x;
    const int b = blockIdx.y;
    const int s0 = blockIdx.x * MT;
    const int lane = tid & 31, wid = tid >> 5;
    const int warp_m = wid & 3, warp_n = wid >> 2;   // 4 m-warps x 2 n-warps

    float* sctx = (float*)(smem + OFF_CTX);
    float* sw2p = (float*)(smem + OFF_W2);
    for (int i = tid; i < ND; i += 256) {
        sctx[i] = g_ctx[b * ND + i];
        sw2p[i] = w2[i];
    }

    ScoreCtx sc;
    sc.gA = g_Ah + ((size_t)b * NS + s0) * ND;
    sc.sbase = smem_u32(smem);

    const float mlen = g_mlen[b];
    float loc[2][2], rowsum[2][2];
#pragma unroll
    for (int mt = 0; mt < 2; mt++)
#pragma unroll
        for (int h = 0; h < 2; h++) {
            float srow = (float)(s0 + warp_m * 32 + mt * 16 + h * 8 + (lane >> 2));
            loc[mt][h] = (srow < mlen) ? (1.0f - srow / mlen) : 1.0f;
            rowsum[mt][h] = 0.f;
        }

    const int a_row = warp_m * 32 + (lane & 7) + ((lane >> 3) & 1) * 8;
    const int a_halfoff = (lane >> 4) * 16;
    const int b_row = warp_n * 64 + (lane & 7) + (lane >> 4) * 8;
    const int b_halfoff = ((lane >> 3) & 1) * 16;

    __syncthreads();

    stage_tiles(sc, 0, 0, 0);
    CP_COMMIT();

    for (int chunk = 0; chunk < NCHUNKS; chunk++) {
        const int nbase = chunk * NTILE;
        float acc[2][8][4];
#pragma unroll
        for (int mt = 0; mt < 2; mt++)
#pragma unroll
            for (int nt = 0; nt < 8; nt++)
#pragma unroll
                for (int j = 0; j < 4; j++) acc[mt][nt][j] = 0.f;

        for (int ks = 0; ks < KSTEPS; ks++) {
            const int buf = ks & 1;
            if (ks + 1 < KSTEPS) {
                stage_tiles(sc, nbase, (ks + 1) * KC, buf ^ 1);
                CP_COMMIT();
                CP_WAIT1();
            } else {
                CP_WAIT0();
            }
            __syncthreads();

            const uint32_t sb = sc.sbase + buf * BUFSZ;
#pragma unroll
            for (int kk = 0; kk < 4; kk++) {
                const int kb = kk * 32;
                uint32_t ar[2][4], br[4][4];
#pragma unroll
                for (int mt = 0; mt < 2; mt++)
                    ldsm4(ar[mt][0], ar[mt][1], ar[mt][2], ar[mt][3],
                          sb + OFF_A + (a_row + mt * 16) * APAD + kb + a_halfoff);
#pragma unroll
                for (int nt2 = 0; nt2 < 4; nt2++)
                    ldsm4(br[nt2][0], br[nt2][1], br[nt2][2], br[nt2][3],
                          sb + OFF_B + (b_row + nt2 * 16) * APAD + kb + b_halfoff);
#pragma unroll
                for (int mt = 0; mt < 2; mt++)
#pragma unroll
                    for (int nt2 = 0; nt2 < 4; nt2++)
#pragma unroll
                        for (int s = 0; s < 2; s++)
                            mma16816(acc[mt][nt2 * 2 + s], ar[mt][0], ar[mt][1], ar[mt][2],
                                     ar[mt][3], br[nt2][2 * s], br[nt2][2 * s + 1]);
            }
            __syncthreads();
        }

        if (chunk + 1 < NCHUNKS) {
            stage_tiles(sc, nbase + NTILE, 0, 0);
            CP_COMMIT();
        }

        // epilogue: tanh (f16x2) + dot with w2
#pragma unroll
        for (int mt = 0; mt < 2; mt++) {
#pragma unroll
            for (int nt = 0; nt < 8; nt++) {
                const int c0 = nbase + warp_n * 64 + nt * 8 + (lane & 3) * 2;
                const float2 cx = *(const float2*)&sctx[c0];
                const float2 wv = *(const float2*)&sw2p[c0];
                {
                    float u0 = fmaf(loc[mt][0], acc[mt][nt][0], cx.x);
                    float u1 = fmaf(loc[mt][0], acc[mt][nt][1], cx.y);
                    __half2 hp = __floats2half2_rn(u0, u1);
                    uint32_t th = tanh2_f16(*(uint32_t*)&hp);
                    float2 tf = __half22float2(*(__half2*)&th);
                    rowsum[mt][0] = fmaf(tf.x, wv.x, fmaf(tf.y, wv.y, rowsum[mt][0]));
                }
                {
                    float u2 = fmaf(loc[mt][1], acc[mt][nt][2], cx.x);
                    float u3 = fmaf(loc[mt][1], acc[mt][nt][3], cx.y);
                    __half2 hp = __floats2half2_rn(u2, u3);
                    uint32_t th = tanh2_f16(*(uint32_t*)&hp);
                    float2 tf = __half22float2(*(__half2*)&th);
                    rowsum[mt][1] = fmaf(tf.x, wv.x, fmaf(tf.y, wv.y, rowsum[mt][1]));
                }
            }
        }
    }

    // reduce quad lanes, then across warp_n via smem
    float* red = (float*)(smem + OFF_RED);
#pragma unroll
    for (int mt = 0; mt < 2; mt++)
#pragma unroll
        for (int h = 0; h < 2; h++) {
            float v = rowsum[mt][h];
            v += __shfl_xor_sync(0xffffffffu, v, 1);
            v += __shfl_xor_sync(0xffffffffu, v, 2);
            if ((lane & 3) == 0) {
                int lrow = warp_m * 32 + mt * 16 + h * 8 + (lane >> 2);
                red[lrow * 2 + warp_n] = v;
            }
        }
    __syncthreads();
    if (tid < MT)
        g_scores[b * NS + s0 + tid] = red[tid * 2] + red[tid * 2 + 1];
}

// ------------------------------------------------------------------
// v_ts + v_ns with inline softmax.  grid (6, 64) = 384 CTAs.
// ------------------------------------------------------------------
__global__ __launch_bounds__(512) void k_vts() {
    int b = blockIdx.y;
    int dc = blockIdx.x;
    int tid = threadIdx.x;
    __shared__ float sw[NS];
    __shared__ float red[512];
    __shared__ float sp[8][64][2];
    float mlen = g_mlen[b];

    float v = g_scores[b * NS + tid];
    red[tid] = v;
    __syncthreads();
    for (int o = 256; o > 0; o >>= 1) {
        if (tid < o) red[tid] = fmaxf(red[tid], red[tid + o]);
        __syncthreads();
    }
    float m = red[0];
    __syncthreads();
    float e = expf(v - m);
    red[tid] = e;
    __syncthreads();
    for (int o = 256; o > 0; o >>= 1) {
        if (tid < o) red[tid] += red[tid + o];
        __syncthreads();
    }
    float inv = 1.0f / red[0];
    float s = (float)tid;
    float l = (s < mlen) ? (1.0f - s / mlen) : 1.0f;
    sw[tid] = e * inv * l;
    __syncthreads();

    int sq = tid >> 6;
    int dd = tid & 63;
    int d = dc * 128 + dd * 2;
    const __half2* p = (const __half2*)(g_Ah + ((size_t)b * NS + sq * 64) * ND + d);
    float a0 = 0.f, a1 = 0.f;
#pragma unroll 8
    for (int s2 = 0; s2 < 64; s2++) {
        float2 h = __half22float2(p[(size_t)s2 * (ND / 2)]);
        float w = sw[sq * 64 + s2];
        a0 = fmaf(w, h.x, a0);
        a1 = fmaf(w, h.y, a1);
    }
    sp[sq][dd][0] = a0;
    sp[sq][dd][1] = a1;
    __syncthreads();
    if (sq == 0) {
        float t0 = 0.f, t1 = 0.f;
#pragma unroll
        for (int i = 0; i < 8; i++) {
            t0 += sp[i][dd][0];
            t1 += sp[i][dd][1];
        }
        g_vns[b * ND + d] = t0 + g_vs[b * ND + d];
        g_vns[b * ND + d + 1] = t1 + g_vs[b * ND + d + 1];
    }
}

// ------------------------------------------------------------------
// v_ms = tanh(v_ns @ Wm + bm)   (fp16 Wm)
// ------------------------------------------------------------------
__global__ __launch_bounds__(512) void k_vms(const float* __restrict__ bm) {
    __shared__ float sp[4][128][2];
    int tid = threadIdx.x;
    int dt = tid & 127;
    int d = blockIdx.x * 128 + dt;
    int q = tid >> 7;
    int b0 = blockIdx.y * 2;
    const float* vb = g_vns + (size_t)b0 * ND;
    int k0 = q * 192;
    float a0 = 0.f, a1 = 0.f;
#pragma unroll 4
    for (int k = 0; k < 192; k++) {
        float w = __half2float(g_Wmh[(size_t)(k0 + k) * ND + d]);
        a0 = fmaf(vb[k0 + k], w, a0);
        a1 = fmaf(vb[ND + k0 + k], w, a1);
    }
    sp[q][dt][0] = a0;
    sp[q][dt][1] = a1;
    __syncthreads();
    if (q == 0) {
        float bb = bm[d];
#pragma unroll
        for (int i = 0; i < 2; i++) {
            float s = sp[0][dt][i] + sp[1][dt][i] + sp[2][dt][i] + sp[3][dt][i] + bb;
            g_vms[(b0 + i) * ND + d] = tanhf(s);
        }
    }
}

// ------------------------------------------------------------------
// logits: 64 CTAs (one per b), 256 thr, smem tree reduce
// ------------------------------------------------------------------
__global__ __launch_bounds__(256) void k_logits(const float* __restrict__ Wd,
                                                const float* __restrict__ bd,
                                                float* __restrict__ out) {
    int b = blockIdx.x;
    int tid = threadIdx.x;
    __shared__ float red[256][3];
    float a0 = 0.f, a1 = 0.f, a2 = 0.f;
    const float* v = g_vms + b * ND;
    for (int d = tid; d < ND; d += 256) {
        float vv = v[d];
        a0 = fmaf(vv, Wd[d * 3 + 0], a0);
        a1 = fmaf(vv, Wd[d * 3 + 1], a1);
        a2 = fmaf(vv, Wd[d * 3 + 2], a2);
    }
    red[tid][0] = a0;
    red[tid][1] = a1;
    red[tid][2] = a2;
    __syncthreads();
    for (int o = 128; o > 0; o >>= 1) {
        if (tid < o) {
            red[tid][0] += red[tid + o][0];
            red[tid][1] += red[tid + o][1];
            red[tid][2] += red[tid + o][2];
        }
        __syncthreads();
    }
    if (tid < 3)
        out[b * 3 + tid] = red[0][tid] + bd[tid];
}

// ------------------------------------------------------------------
// launch  (6 kernels)
// ------------------------------------------------------------------
extern "C" void kernel_launch(void* const* d_in, const int* in_sizes, int n_in,
                              void* d_out, int out_size) {
    (void)in_sizes; (void)n_in; (void)out_size;
    const float* mem  = (const float*)d_in[0];
    const float* asp  = (const float*)d_in[1];
    const int* ids    = (const int*)d_in[2];
    const int* tids   = (const int*)d_in[3];
    const float* W1 = (const float*)d_in[4];
    const float* b1 = (const float*)d_in[5];
    const float* w2 = (const float*)d_in[6];
    const float* Wm = (const float*)d_in[7];
    const float* bm = (const float*)d_in[8];
    const float* Wd = (const float*)d_in[9];
    const float* bd = (const float*)d_in[10];
    float* out = (float*)d_out;

    cudaFuncSetAttribute(k_scores, cudaFuncAttributeMaxDynamicSharedMemorySize, SMEMSZ);

    k_head<<<1456, 512>>>(mem, asp, ids, tids, W1, Wm);
    k_ctx<<<dim3(ND / 128, NB / 2), 512>>>(b1);
    k_scores<<<dim3(NS / MT, NB), 256, SMEMSZ>>>(w2);
    k_vts<<<dim3(6, NB), 512>>>();
    k_vms<<<dim3(ND / 128, NB / 2), 512>>>(bm);
    k_logits<<<NB, 256>>>(Wd, bd, out);
}